// round 13
// baseline (speedup 1.0000x reference)
#include <cuda_runtime.h>
#include <cuda_bf16.h>
#include <cuda_fp16.h>
#include <cstdint>

#define N_NODES 8192
#define FIN     512
#define FOUT    256
#define BKC     64                   // K-chunk
#define NCHUNK  (N_NODES / BKC)      // 128

// ---------------------------------------------------------------------------
// Device scratch
// ---------------------------------------------------------------------------
__device__ float g_h[(size_t)N_NODES * FOUT];          // 8 MB   h = x@W
__device__ float g_s[2 * N_NODES];                     // s_src | s_dst
__device__ float g_smax = -3.0e38f;                    // max_j s_dst (atomicMax)
__device__ __half g_hT[(size_t)FOUT * N_NODES];        // 4 MB   h^T fp16
__device__ __half g_w[(size_t)N_NODES * N_NODES];      // 128 MB weight matrix
__device__ float g_den[N_NODES];                       // row denominators

// mish(u) = u*(t^2+2t)/(t^2+2t+2), t=e^u
__device__ __forceinline__ float fast_mish(float u) {
    if (u > 30.f) return u;
    float t = __expf(u);
    float v = t * (t + 2.f);
    return u * __fdividef(v, v + 2.f);
}
__device__ __forceinline__ uint32_t smem_u32(const void* p) {
    uint32_t a;
    asm("{ .reg .u64 t; cvta.to.shared.u64 t, %1; cvt.u32.u64 %0, t; }" : "=r"(a) : "l"(p));
    return a;
}
__device__ __forceinline__ void atomic_max_float(float* addr, float val) {
    int old = __float_as_int(*addr);
    while (__int_as_float(old) < val) {
        int prev = atomicCAS((int*)addr, old, __float_as_int(val));
        if (prev == old) break;
        old = prev;
    }
}
#define SW128(x) ((x) ^ (((x) >> 3) & 0x70))

// ---- baseline-PTX tensor / async ops (compute_103-safe) --------------------
__device__ __forceinline__ void ldsm4(uint32_t* r, uint32_t addr) {
    asm volatile("ldmatrix.sync.aligned.m8n8.x4.shared.b16 {%0,%1,%2,%3}, [%4];"
                 : "=r"(r[0]), "=r"(r[1]), "=r"(r[2]), "=r"(r[3]) : "r"(addr));
}
__device__ __forceinline__ void mma_f16(float* d, const uint32_t* a,
                                        uint32_t b0, uint32_t b1) {
    asm volatile("mma.sync.aligned.m16n8k16.row.col.f32.f16.f16.f32 "
                 "{%0,%1,%2,%3}, {%4,%5,%6,%7}, {%8,%9}, {%0,%1,%2,%3};"
                 : "+f"(d[0]), "+f"(d[1]), "+f"(d[2]), "+f"(d[3])
                 : "r"(a[0]), "r"(a[1]), "r"(a[2]), "r"(a[3]), "r"(b0), "r"(b1));
}
__device__ __forceinline__ void cpa16(uint32_t s, const void* g) {
    asm volatile("cp.async.cg.shared.global [%0], [%1], 16;" :: "r"(s), "l"(g));
}
#define CPA_COMMIT() asm volatile("cp.async.commit_group;" ::: "memory")
#define CPA_WAIT1()  asm volatile("cp.async.wait_group 1;" ::: "memory")
#define CPA_WAIT0()  asm volatile("cp.async.wait_group 0;" ::: "memory")

// ---------------------------------------------------------------------------
// Launch 1: h = x @ W  (FFMA SGEMM) + fused h^T fp16 emission
// ---------------------------------------------------------------------------
__global__ __launch_bounds__(256) void k_sgemm_xw(
    const float* __restrict__ X, const float* __restrict__ W)
{
    __shared__ float As[16][64];
    __shared__ float Bs[16][64];
    __shared__ __half ht[64][66];
    const int bn = blockIdx.x * 64, bm = blockIdx.y * 64;
    const int tid = threadIdx.x, tx = tid & 15, ty = tid >> 4;
    float acc[4][4];
#pragma unroll
    for (int r = 0; r < 4; r++)
#pragma unroll
        for (int c = 0; c < 4; c++) acc[r][c] = 0.f;
    for (int k0 = 0; k0 < FIN; k0 += 16) {
#pragma unroll
        for (int i = tid; i < 1024; i += 256) {
            int m = i >> 4, k = i & 15;
            As[k][m] = X[(size_t)(bm + m) * FIN + k0 + k];
        }
#pragma unroll
        for (int i = tid; i < 1024; i += 256) {
            int k = i >> 6, n = i & 63;
            Bs[k][n] = W[(size_t)(k0 + k) * FOUT + bn + n];
        }
        __syncthreads();
#pragma unroll
        for (int k = 0; k < 16; k++) {
            float4 a4 = *(const float4*)&As[k][ty * 4];
            float4 b4 = *(const float4*)&Bs[k][tx * 4];
            float a[4] = {a4.x, a4.y, a4.z, a4.w};
            float b[4] = {b4.x, b4.y, b4.z, b4.w};
#pragma unroll
            for (int r = 0; r < 4; r++)
#pragma unroll
                for (int c = 0; c < 4; c++) acc[r][c] = fmaf(a[r], b[c], acc[r][c]);
        }
        __syncthreads();
    }
#pragma unroll
    for (int r = 0; r < 4; r++) {
        float4 o = {acc[r][0], acc[r][1], acc[r][2], acc[r][3]};
        *(float4*)&g_h[(size_t)(bm + ty * 4 + r) * FOUT + bn + tx * 4] = o;
#pragma unroll
        for (int c = 0; c < 4; c++)
            ht[ty * 4 + r][tx * 4 + c] = __float2half_rn(acc[r][c]);
    }
    __syncthreads();
    // coalesced transposed store: g_hT[n][m]
#pragma unroll
    for (int i = tid; i < 4096; i += 256) {
        const int n = i >> 6, m = i & 63;
        g_hT[(size_t)(bn + n) * N_NODES + bm + m] = ht[m][n];
    }
}

// ---------------------------------------------------------------------------
// Launch 2: s_src / s_dst + global max(s_dst)
// ---------------------------------------------------------------------------
__global__ __launch_bounds__(256) void k_scores(const float* __restrict__ A)
{
    const int row = blockIdx.x * 8 + (threadIdx.x >> 5);
    const int lane = threadIdx.x & 31;
    const float4* h4 = (const float4*)(g_h + (size_t)row * FOUT);
    const float4* a14 = (const float4*)A;
    const float4* a24 = (const float4*)(A + FOUT);
    float s1 = 0.f, s2 = 0.f;
#pragma unroll
    for (int i = 0; i < 2; i++) {
        int idx = lane + i * 32;
        float4 h = h4[idx], a1 = a14[idx], a2 = a24[idx];
        s1 += h.x * a1.x + h.y * a1.y + h.z * a1.z + h.w * a1.w;
        s2 += h.x * a2.x + h.y * a2.y + h.z * a2.z + h.w * a2.w;
    }
#pragma unroll
    for (int off = 16; off; off >>= 1) {
        s1 += __shfl_down_sync(0xffffffffu, s1, off);
        s2 += __shfl_down_sync(0xffffffffu, s2, off);
    }
    if (lane == 0) {
        g_s[row] = s1;
        g_s[N_NODES + row] = s2;
        atomic_max_float(&g_smax, s2);
    }
}

// ---------------------------------------------------------------------------
// Launch 3: W = exp(mish(s_i+s_j)-c_i) fp16 + row denominators (adj read raw).
// ---------------------------------------------------------------------------
__global__ __launch_bounds__(256) void k_wgen(const int* __restrict__ adj)
{
    const int lane = threadIdx.x & 31, wid = threadIdx.x >> 5;
    const int row = blockIdx.x * 8 + wid;
    const float ssrc = g_s[row];
    const float ci = fmaxf(ssrc + g_smax, 0.f);
    const float* __restrict__ sdst = g_s + N_NODES;
    const int4* __restrict__ arow = (const int4*)(adj + (size_t)row * N_NODES);
    __half* __restrict__ wrow = g_w + (size_t)row * N_NODES;
    float rsum = 0.f;
#pragma unroll 4
    for (int q = 0; q < 64; q++) {
        const int j4 = q * 32 + lane;        // int4 / float4 index
        int4   av = __ldg(arow + j4);
        float4 sv = __ldg((const float4*)sdst + j4);
        float w0 = (av.x > 0) ? __expf(fast_mish(ssrc + sv.x) - ci) : 0.f;
        float w1 = (av.y > 0) ? __expf(fast_mish(ssrc + sv.y) - ci) : 0.f;
        float w2 = (av.z > 0) ? __expf(fast_mish(ssrc + sv.z) - ci) : 0.f;
        float w3 = (av.w > 0) ? __expf(fast_mish(ssrc + sv.w) - ci) : 0.f;
        __half2 p01 = __floats2half2_rn(w0, w1);
        __half2 p23 = __floats2half2_rn(w2, w3);
        float2 f01 = __half22float2(p01);
        float2 f23 = __half22float2(p23);
        rsum += (f01.x + f01.y) + (f23.x + f23.y);
        uint2 pk = {*(uint32_t*)&p01, *(uint32_t*)&p23};
        *(uint2*)(wrow + j4 * 4) = pk;
    }
#pragma unroll
    for (int o = 16; o; o >>= 1) rsum += __shfl_down_sync(0xffffffffu, rsum, o);
    if (lane == 0) g_den[row] = rsum;
}

// ---------------------------------------------------------------------------
// Launch 4: fp16 GEMM  out = mish( (W @ hT^T) / den ).
// Grid (128, 2) = 256 CTAs, 128 thr (4 warps, 2m x 2n), 3 CTAs/SM.
// CTA: M=64, N=128, K=8192. Warp tile 32x64 -> 192 B LDSM per HMMA.
// Stage (24KB x3): A [64x64] 8K | B [128x64] 16K. 3-stage cp.async, wait_group 1.
// ---------------------------------------------------------------------------
#define GST    24576
#define GOFF_B 8192
#define GEMM_SMEM (3 * GST)   // 73728 -> 3 CTAs/SM

__global__ __launch_bounds__(128, 3) void k_gemm(float* __restrict__ out)
{
    extern __shared__ char smem[];
    __shared__ float denf[64];
    const uint32_t sb = smem_u32(smem);
    const int tid = threadIdx.x;
    const int lane = tid & 31;
    const int wid = tid >> 5;

    const int row0  = blockIdx.x * 64;
    const int nbase = blockIdx.y * 128;

    // cp.async mappings (128 threads):
    // A: 64 rows x 8 segs -> thread = row (tid>>1), 4 segs at (tid&1)*64
    const int ar = tid >> 1;
    const uint32_t aoff = (uint32_t)(tid & 1) * 64;
    const char* __restrict__ asrc = (const char*)(g_w + (size_t)(row0 + ar) * N_NODES) + aoff;
    const uint32_t ab = (uint32_t)ar * 128 + aoff;
    // B: 128 rows x 8 segs -> thread = row, 8 segs
    const char* __restrict__ bsrc = (const char*)(g_hT + (size_t)(nbase + tid) * N_NODES);
    const uint32_t bb = (uint32_t)tid * 128;

    // consumer mapping: warp (wm, wn): 32x64 tile
    const int wm = wid & 1;
    const int wn = wid >> 1;            // 0..1
    const int ksw = lane & 7;
    const int alsel = lane >> 4;
    const int bg = lane >> 3;
    const int kb0 = bg & 1;
    const uint32_t arow  = (uint32_t)(wm * 32 + (lane & 15)) * 128;
    const uint32_t brow0 = GOFF_B +
        (uint32_t)(wn * 64 + (lane & 7) + ((bg & 2) << 2)) * 128;

    if (tid < 64) denf[tid] = g_den[row0 + tid];

    float acc[2][8][4];
#pragma unroll
    for (int mt = 0; mt < 2; mt++)
#pragma unroll
        for (int nt = 0; nt < 8; nt++)
#pragma unroll
            for (int q = 0; q < 4; q++) acc[mt][nt][q] = 0.f;

    uint32_t Af[2][2][4];
    uint32_t Bf[2][4][4];

#define G_PROD(st_, c_)                                                          \
    {                                                                            \
        const uint32_t db = sb + (st_) * GST;                                    \
        const char* as = asrc + (size_t)(c_) * 128;                              \
        _Pragma("unroll")                                                        \
        for (int t = 0; t < 4; t++)                                              \
            cpa16(db + SW128(ab + t * 16), as + t * 16);                         \
        const char* bs = bsrc + (size_t)(c_) * 128;                              \
        _Pragma("unroll")                                                        \
        for (int t = 0; t < 8; t++)                                              \
            cpa16(db + GOFF_B + SW128(bb + t * 16), bs + t * 16);                \
        CPA_COMMIT();                                                            \
    }

// A fragments: consecutive m16 fragments are 16 rows apart = 2048 bytes.
// B fragments: consecutive n16 fragments are 16 rows apart = 2048 bytes.
#define G_FRAGS(base_, buf_, ks_)                                                \
    {                                                                            \
        const int kcA = (ks_) * 2 + alsel;                                       \
        const uint32_t ao = (uint32_t)((kcA ^ ksw) << 4);                        \
        ldsm4(Af[buf_][0], (base_) + arow + ao);                                 \
        ldsm4(Af[buf_][1], (base_) + arow + 2048 + ao);                          \
        const int kcB = (ks_) * 2 + kb0;                                         \
        const uint32_t bo = (uint32_t)((kcB ^ ksw) << 4);                        \
        ldsm4(Bf[buf_][0], (base_) + brow0 + bo);                                \
        ldsm4(Bf[buf_][1], (base_) + brow0 + 2048 + bo);                         \
        ldsm4(Bf[buf_][2], (base_) + brow0 + 4096 + bo);                         \
        ldsm4(Bf[buf_][3], (base_) + brow0 + 6144 + bo);                         \
    }

    // ---- prologue: 2 chunks in flight ----
    G_PROD(0, 0);
    G_PROD(1, 1);

    for (int c = 0; c < NCHUNK; c++) {
        const int st = c % 3;
        if (c + 1 >= NCHUNK) { CPA_WAIT0(); } else { CPA_WAIT1(); }
        __syncthreads();
        if (c + 2 < NCHUNK) G_PROD((c + 2) % 3, c + 2);

        const uint32_t sbase = sb + st * GST;
        G_FRAGS(sbase, 0, 0);
#pragma unroll
        for (int ks = 0; ks < 4; ks++) {
            const int cur = ks & 1;
            if (ks < 3) G_FRAGS(sbase, cur ^ 1, ks + 1);
#pragma unroll
            for (int ng = 0; ng < 4; ng++) {
                mma_f16(acc[0][ng * 2],     Af[cur][0], Bf[cur][ng][0], Bf[cur][ng][1]);
                mma_f16(acc[0][ng * 2 + 1], Af[cur][0], Bf[cur][ng][2], Bf[cur][ng][3]);
                mma_f16(acc[1][ng * 2],     Af[cur][1], Bf[cur][ng][0], Bf[cur][ng][1]);
                mma_f16(acc[1][ng * 2 + 1], Af[cur][1], Bf[cur][ng][2], Bf[cur][ng][3]);
            }
        }
    }

    // ---- epilogue: normalize + mish -> out ----
#pragma unroll
    for (int mt = 0; mt < 2; mt++) {
        const int lr = wm * 32 + mt * 16 + (lane >> 2);
        const float inv0 = __fdividef(1.f, denf[lr]);
        const float inv1 = __fdividef(1.f, denf[lr + 8]);
        float* o0 = out + (size_t)(row0 + lr) * FOUT + nbase;
        float* o1 = out + (size_t)(row0 + lr + 8) * FOUT + nbase;
#pragma unroll
        for (int nt = 0; nt < 8; nt++) {
            const int col = wn * 64 + nt * 8 + (lane & 3) * 2;
            float2 v0 = {fast_mish(acc[mt][nt][0] * inv0),
                         fast_mish(acc[mt][nt][1] * inv0)};
            float2 v1 = {fast_mish(acc[mt][nt][2] * inv1),
                         fast_mish(acc[mt][nt][3] * inv1)};
            *(float2*)&o0[col] = v0;
            *(float2*)&o1[col] = v1;
        }
    }
#undef G_PROD
#undef G_FRAGS
}

// ---------------------------------------------------------------------------
extern "C" void kernel_launch(void* const* d_in, const int* in_sizes, int n_in,
                              void* d_out, int out_size)
{
    const float* x   = (const float*)d_in[0];   // [8192, 512]
    const int*   adj = (const int*)  d_in[1];   // [8192, 8192]
    const float* w   = (const float*)d_in[2];   // [512, 256]
    const float* a   = (const float*)d_in[3];   // [512, 1]
    float* out = (float*)d_out;                 // [8192, 256]

    cudaFuncSetAttribute(k_gemm, cudaFuncAttributeMaxDynamicSharedMemorySize,
                         GEMM_SMEM);

    k_sgemm_xw<<<dim3(FOUT / 64, N_NODES / 64), 256>>>(x, w);   // launch 1
    k_scores<<<N_NODES / 8, 256>>>(a);                          // launch 2
    k_wgen<<<N_NODES / 8, 256>>>(adj);                          // launch 3
    k_gemm<<<dim3(128, 2), 128, GEMM_SMEM>>>(out);              // launch 4 (profiled)
}

// round 14
// speedup vs baseline: 1.1900x; 1.1900x over previous
#include <cuda_runtime.h>
#include <cuda_bf16.h>
#include <cuda_fp16.h>
#include <cstdint>

#define N_NODES 8192
#define FIN     512
#define FOUT    256
#define BKC     64                   // K-chunk
#define NCHUNK  (N_NODES / BKC)      // 128

// ---------------------------------------------------------------------------
// Device scratch
// ---------------------------------------------------------------------------
__device__ float g_h[(size_t)N_NODES * FOUT];          // 8 MB   h = x@W
__device__ float g_s[2 * N_NODES];                     // s_src | s_dst
__device__ float g_smax = -3.0e38f;                    // max_j s_dst (atomicMax)
__device__ __half g_hT[(size_t)FOUT * N_NODES];        // 4 MB   h^T fp16
__device__ __half g_w[(size_t)N_NODES * N_NODES];      // 128 MB weight matrix
__device__ float g_den[N_NODES];                       // row denominators

// mish(u) = u*(t^2+2t)/(t^2+2t+2), t=e^u
__device__ __forceinline__ float fast_mish(float u) {
    if (u > 30.f) return u;
    float t = __expf(u);
    float v = t * (t + 2.f);
    return u * __fdividef(v, v + 2.f);
}
__device__ __forceinline__ uint32_t smem_u32(const void* p) {
    uint32_t a;
    asm("{ .reg .u64 t; cvta.to.shared.u64 t, %1; cvt.u32.u64 %0, t; }" : "=r"(a) : "l"(p));
    return a;
}
__device__ __forceinline__ void atomic_max_float(float* addr, float val) {
    int old = __float_as_int(*addr);
    while (__int_as_float(old) < val) {
        int prev = atomicCAS((int*)addr, old, __float_as_int(val));
        if (prev == old) break;
        old = prev;
    }
}
#define SW128(x) ((x) ^ (((x) >> 3) & 0x70))

// ---- baseline-PTX tensor / async ops (compute_103-safe) --------------------
__device__ __forceinline__ void ldsm4(uint32_t* r, uint32_t addr) {
    asm volatile("ldmatrix.sync.aligned.m8n8.x4.shared.b16 {%0,%1,%2,%3}, [%4];"
                 : "=r"(r[0]), "=r"(r[1]), "=r"(r[2]), "=r"(r[3]) : "r"(addr));
}
__device__ __forceinline__ void mma_f16(float* d, const uint32_t* a,
                                        uint32_t b0, uint32_t b1) {
    asm volatile("mma.sync.aligned.m16n8k16.row.col.f32.f16.f16.f32 "
                 "{%0,%1,%2,%3}, {%4,%5,%6,%7}, {%8,%9}, {%0,%1,%2,%3};"
                 : "+f"(d[0]), "+f"(d[1]), "+f"(d[2]), "+f"(d[3])
                 : "r"(a[0]), "r"(a[1]), "r"(a[2]), "r"(a[3]), "r"(b0), "r"(b1));
}
__device__ __forceinline__ void cpa16(uint32_t s, const void* g) {
    asm volatile("cp.async.cg.shared.global [%0], [%1], 16;" :: "r"(s), "l"(g));
}
#define CPA_COMMIT() asm volatile("cp.async.commit_group;" ::: "memory")
#define CPA_WAIT1()  asm volatile("cp.async.wait_group 1;" ::: "memory")
#define CPA_WAIT0()  asm volatile("cp.async.wait_group 0;" ::: "memory")

__device__ __forceinline__ uint32_t pack_hilo(float a, float b, uint32_t& lo) {
    __half ha = __float2half_rn(a), hb = __float2half_rn(b);
    __half la = __float2half_rn(a - __half2float(ha));
    __half lb = __float2half_rn(b - __half2float(hb));
    lo = (uint32_t)__half_as_ushort(la) | ((uint32_t)__half_as_ushort(lb) << 16);
    return (uint32_t)__half_as_ushort(ha) | ((uint32_t)__half_as_ushort(hb) << 16);
}

// ---------------------------------------------------------------------------
// Launch 1: h = x @ W via HMMA, 3-term fp16 hi/lo split; emits g_h + g_hT.
// Grid (64, 2) = 128 CTAs, 256 thr (8 warps 4m x 2n, warp tile 32x64).
// CTA tile M=128, N=128, K=512 in 8 chunks of 64.
// Smem: Ah 16K | Al 16K | Bh 16K | Bl 16K = 64KB (single stage).
// ---------------------------------------------------------------------------
#define XT_AL 16384
#define XT_BH 32768
#define XT_BL 49152
#define XT_SMEM 65536

__global__ __launch_bounds__(256) void k_xw_tc(
    const float* __restrict__ X, const float* __restrict__ W)
{
    extern __shared__ char smem[];
    const uint32_t sb = smem_u32(smem);
    const int tid = threadIdx.x;
    const int lane = tid & 31;
    const int wid = tid >> 5;
    const int m0 = blockIdx.x * 128;
    const int n0 = blockIdx.y * 128;

    // consumer mapping: warp (wm, wn), warp tile 32x64
    const int wm = wid & 3;
    const int wn = wid >> 2;
    const int ksw = lane & 7;
    const int alsel = lane >> 4;
    const int bg = lane >> 3;
    const int kb0 = bg & 1;
    const uint32_t arow  = (uint32_t)(wm * 32 + (lane & 15)) * 128;
    const uint32_t brow0 = XT_BH + (uint32_t)(wn * 64 + (lane & 7) + ((bg & 2) << 2)) * 128;

    float acc[2][8][4];
#pragma unroll
    for (int mt = 0; mt < 2; mt++)
#pragma unroll
        for (int nt = 0; nt < 8; nt++)
#pragma unroll
            for (int q = 0; q < 4; q++) acc[mt][nt][q] = 0.f;

    for (int c = 0; c < 8; c++) {
        const int k0 = c * 64;
        // ---- load A tile: x[m0+row][k0 + kh*32 .. +32] -> Ah/Al ----
        {
            const int row = tid >> 1, kh = tid & 1;
            const float4* xs = (const float4*)(X + (size_t)(m0 + row) * FIN + k0 + kh * 32);
#pragma unroll
            for (int i = 0; i < 8; i++) {
                float4 v = __ldg(xs + i);
                uint32_t l01, l23;
                uint32_t h01 = pack_hilo(v.x, v.y, l01);
                uint32_t h23 = pack_hilo(v.z, v.w, l23);
                uint32_t off = SW128((uint32_t)row * 128 + (kh * 32 + i * 4) * 2);
                *(uint2*)(smem + off) = make_uint2(h01, h23);
                *(uint2*)(smem + XT_AL + off) = make_uint2(l01, l23);
            }
        }
        // ---- load B tile: W[k0+k][n0+n] transposed -> Bh/Bl [n][k] ----
        {
            const int n = tid & 127, kh = tid >> 7;
#pragma unroll 8
            for (int kk = 0; kk < 32; kk++) {
                const int k = kh * 32 + kk;
                float v = __ldg(W + (size_t)(k0 + k) * FOUT + n0 + n);
                __half hv = __float2half_rn(v);
                __half lv = __float2half_rn(v - __half2float(hv));
                uint32_t off = SW128((uint32_t)n * 128 + k * 2);
                *(__half*)(smem + XT_BH + off) = hv;
                *(__half*)(smem + XT_BL + off) = lv;
            }
        }
        __syncthreads();

        // ---- consume 4 k16 slices, 3 split terms ----
#pragma unroll
        for (int ks = 0; ks < 4; ks++) {
            uint32_t Ah[2][4], Al[2][4], Bh[4][4], Bl[4][4];
            const int kcA = ks * 2 + alsel;
            const uint32_t ao = (uint32_t)((kcA ^ ksw) << 4);
            ldsm4(Ah[0], sb + arow + ao);
            ldsm4(Ah[1], sb + arow + 2048 + ao);
            ldsm4(Al[0], sb + XT_AL + arow + ao);
            ldsm4(Al[1], sb + XT_AL + arow + 2048 + ao);
            const int kcB = ks * 2 + kb0;
            const uint32_t bo = (uint32_t)((kcB ^ ksw) << 4);
#pragma unroll
            for (int ng = 0; ng < 4; ng++) {
                ldsm4(Bh[ng], sb + brow0 + ng * 2048 + bo);
                ldsm4(Bl[ng], sb + brow0 + 16384 + ng * 2048 + bo);
            }
#pragma unroll
            for (int ng = 0; ng < 4; ng++) {
#pragma unroll
                for (int mt = 0; mt < 2; mt++) {
                    mma_f16(acc[mt][ng * 2],     Ah[mt], Bh[ng][0], Bh[ng][1]);
                    mma_f16(acc[mt][ng * 2 + 1], Ah[mt], Bh[ng][2], Bh[ng][3]);
                    mma_f16(acc[mt][ng * 2],     Al[mt], Bh[ng][0], Bh[ng][1]);
                    mma_f16(acc[mt][ng * 2 + 1], Al[mt], Bh[ng][2], Bh[ng][3]);
                    mma_f16(acc[mt][ng * 2],     Ah[mt], Bl[ng][0], Bl[ng][1]);
                    mma_f16(acc[mt][ng * 2 + 1], Ah[mt], Bl[ng][2], Bl[ng][3]);
                }
            }
        }
        __syncthreads();
    }

    // ---- epilogue 1: g_h fp32 direct stores ----
#pragma unroll
    for (int mt = 0; mt < 2; mt++) {
        const int lr = wm * 32 + mt * 16 + (lane >> 2);
#pragma unroll
        for (int nt = 0; nt < 8; nt++) {
            const int col = n0 + wn * 64 + nt * 8 + (lane & 3) * 2;
            float2 v0 = {acc[mt][nt][0], acc[mt][nt][1]};
            float2 v1 = {acc[mt][nt][2], acc[mt][nt][3]};
            *(float2*)&g_h[(size_t)(m0 + lr) * FOUT + col] = v0;
            *(float2*)&g_h[(size_t)(m0 + lr + 8) * FOUT + col] = v1;
        }
    }

    // ---- epilogue 2: g_hT fp16 via smem transpose (reuse stage memory) ----
    {
        __half* ht = (__half*)smem;     // [128][130]
#pragma unroll
        for (int mt = 0; mt < 2; mt++) {
            const int lr = wm * 32 + mt * 16 + (lane >> 2);
#pragma unroll
            for (int nt = 0; nt < 8; nt++) {
                const int col = wn * 64 + nt * 8 + (lane & 3) * 2;
                ht[lr * 130 + col]           = __float2half_rn(acc[mt][nt][0]);
                ht[lr * 130 + col + 1]       = __float2half_rn(acc[mt][nt][1]);
                ht[(lr + 8) * 130 + col]     = __float2half_rn(acc[mt][nt][2]);
                ht[(lr + 8) * 130 + col + 1] = __float2half_rn(acc[mt][nt][3]);
            }
        }
        __syncthreads();
#pragma unroll
        for (int i = tid; i < 16384; i += 256) {
            const int n = i >> 7, m = i & 127;
            g_hT[(size_t)(n0 + n) * N_NODES + m0 + m] = ht[m * 130 + n];
        }
    }
}

// ---------------------------------------------------------------------------
// Launch 2: s_src / s_dst + global max(s_dst)
// ---------------------------------------------------------------------------
__global__ __launch_bounds__(256) void k_scores(const float* __restrict__ A)
{
    const int row = blockIdx.x * 8 + (threadIdx.x >> 5);
    const int lane = threadIdx.x & 31;
    const float4* h4 = (const float4*)(g_h + (size_t)row * FOUT);
    const float4* a14 = (const float4*)A;
    const float4* a24 = (const float4*)(A + FOUT);
    float s1 = 0.f, s2 = 0.f;
#pragma unroll
    for (int i = 0; i < 2; i++) {
        int idx = lane + i * 32;
        float4 h = h4[idx], a1 = a14[idx], a2 = a24[idx];
        s1 += h.x * a1.x + h.y * a1.y + h.z * a1.z + h.w * a1.w;
        s2 += h.x * a2.x + h.y * a2.y + h.z * a2.z + h.w * a2.w;
    }
#pragma unroll
    for (int off = 16; off; off >>= 1) {
        s1 += __shfl_down_sync(0xffffffffu, s1, off);
        s2 += __shfl_down_sync(0xffffffffu, s2, off);
    }
    if (lane == 0) {
        g_s[row] = s1;
        g_s[N_NODES + row] = s2;
        atomic_max_float(&g_smax, s2);
    }
}

// ---------------------------------------------------------------------------
// Launch 3: W = exp(mish(s_i+s_j)-c_i) fp16 + row denominators (adj read raw).
// ---------------------------------------------------------------------------
__global__ __launch_bounds__(256) void k_wgen(const int* __restrict__ adj)
{
    const int lane = threadIdx.x & 31, wid = threadIdx.x >> 5;
    const int row = blockIdx.x * 8 + wid;
    const float ssrc = g_s[row];
    const float ci = fmaxf(ssrc + g_smax, 0.f);
    const float* __restrict__ sdst = g_s + N_NODES;
    const int4* __restrict__ arow = (const int4*)(adj + (size_t)row * N_NODES);
    __half* __restrict__ wrow = g_w + (size_t)row * N_NODES;
    float rsum = 0.f;
#pragma unroll 4
    for (int q = 0; q < 64; q++) {
        const int j4 = q * 32 + lane;        // int4 / float4 index
        int4   av = __ldg(arow + j4);
        float4 sv = __ldg((const float4*)sdst + j4);
        float w0 = (av.x > 0) ? __expf(fast_mish(ssrc + sv.x) - ci) : 0.f;
        float w1 = (av.y > 0) ? __expf(fast_mish(ssrc + sv.y) - ci) : 0.f;
        float w2 = (av.z > 0) ? __expf(fast_mish(ssrc + sv.z) - ci) : 0.f;
        float w3 = (av.w > 0) ? __expf(fast_mish(ssrc + sv.w) - ci) : 0.f;
        __half2 p01 = __floats2half2_rn(w0, w1);
        __half2 p23 = __floats2half2_rn(w2, w3);
        float2 f01 = __half22float2(p01);
        float2 f23 = __half22float2(p23);
        rsum += (f01.x + f01.y) + (f23.x + f23.y);
        uint2 pk = {*(uint32_t*)&p01, *(uint32_t*)&p23};
        *(uint2*)(wrow + j4 * 4) = pk;
    }
#pragma unroll
    for (int o = 16; o; o >>= 1) rsum += __shfl_down_sync(0xffffffffu, rsum, o);
    if (lane == 0) g_den[row] = rsum;
}

// ---------------------------------------------------------------------------
// Launch 4: fp16 GEMM  out = mish( (W @ hT^T) / den ).   [R12 config]
// Grid (128, 2) = 256 CTAs, 256 thr. CTA: M=64, N=128, K=8192.
// Stage (24KB x3): A [64x64] 8K | B [128x64] 16K. 3-stage cp.async, wait_group 1.
// Warp grid 2(m) x 4(n); warp tile 32x32.
// ---------------------------------------------------------------------------
#define GST    24576
#define GOFF_B 8192
#define GEMM_SMEM (3 * GST)   // 73728 -> 2 CTAs/SM

__global__ __launch_bounds__(256, 2) void k_gemm(float* __restrict__ out)
{
    extern __shared__ char smem[];
    __shared__ float denf[64];
    const uint32_t sb = smem_u32(smem);
    const int tid = threadIdx.x;
    const int lane = tid & 31;
    const int wid = tid >> 5;

    const int row0  = blockIdx.x * 64;
    const int nbase = blockIdx.y * 128;

    // cp.async mappings: A = 64 rows x 128B (2 segs/thread), B = 128 rows x 128B (4/thread)
    const int ar = tid >> 3;
    const uint32_t aoff = (uint32_t)(tid & 7) * 16;
    const char* __restrict__ asrc0 = (const char*)(g_w + (size_t)(row0 + ar) * N_NODES) + aoff;
    const char* __restrict__ asrc1 = (const char*)(g_w + (size_t)(row0 + ar + 32) * N_NODES) + aoff;
    const uint32_t adst0 = SW128((uint32_t)ar * 128 + aoff);
    const uint32_t adst1 = SW128((uint32_t)(ar + 32) * 128 + aoff);
    const int brow_p = tid & 127, bhalf = tid >> 7;
    const char* __restrict__ bsrc =
        (const char*)(g_hT + (size_t)(nbase + brow_p) * N_NODES) + bhalf * 64;
    const uint32_t bb = (uint32_t)brow_p * 128 + bhalf * 64;

    // consumer mapping: warp (wm, wn): 32x32 tile
    const int wm = wid & 1;
    const int wn = wid >> 1;            // 0..3
    const int ksw = lane & 7;
    const int alsel = lane >> 4;
    const int bg = lane >> 3;
    const int kb0 = bg & 1;
    const uint32_t arow  = (uint32_t)(wm * 32 + (lane & 15)) * 128;
    const uint32_t brow0 = GOFF_B +
        (uint32_t)(wn * 32 + (lane & 7) + ((bg & 2) << 2)) * 128;

    if (tid < 64) denf[tid] = g_den[row0 + tid];

    float acc[2][4][4];
#pragma unroll
    for (int mt = 0; mt < 2; mt++)
#pragma unroll
        for (int nt = 0; nt < 4; nt++)
#pragma unroll
            for (int q = 0; q < 4; q++) acc[mt][nt][q] = 0.f;

    uint32_t Af[2][2][4];
    uint32_t Bf[2][2][4];

#define G_PROD(st_, c_)                                                          \
    {                                                                            \
        const uint32_t db = sb + (st_) * GST;                                    \
        cpa16(db + adst0, asrc0 + (size_t)(c_) * 128);                           \
        cpa16(db + adst1, asrc1 + (size_t)(c_) * 128);                           \
        const char* bs = bsrc + (size_t)(c_) * 128;                              \
        _Pragma("unroll")                                                        \
        for (int t = 0; t < 4; t++)                                              \
            cpa16(db + GOFF_B + SW128(bb + t * 16), bs + t * 16);                \
        CPA_COMMIT();                                                            \
    }

// A fragments: consecutive m16 fragments are 16 rows apart = 2048 bytes.
#define G_FRAGS(base_, buf_, ks_)                                                \
    {                                                                            \
        const int kcA = (ks_) * 2 + alsel;                                       \
        const uint32_t ao = (uint32_t)((kcA ^ ksw) << 4);                        \
        ldsm4(Af[buf_][0], (base_) + arow + ao);                                 \
        ldsm4(Af[buf_][1], (base_) + arow + 2048 + ao);                          \
        const int kcB = (ks_) * 2 + kb0;                                         \
        const uint32_t bo = (uint32_t)((kcB ^ ksw) << 4);                        \
        ldsm4(Bf[buf_][0], (base_) + brow0 + bo);                                \
        ldsm4(Bf[buf_][1], (base_) + brow0 + 2048 + bo);                         \
    }

    // ---- prologue: 2 chunks in flight ----
    G_PROD(0, 0);
    G_PROD(1, 1);

    for (int c = 0; c < NCHUNK; c++) {
        const int st = c % 3;
        if (c + 1 >= NCHUNK) { CPA_WAIT0(); } else { CPA_WAIT1(); }
        __syncthreads();
        if (c + 2 < NCHUNK) G_PROD((c + 2) % 3, c + 2);

        const uint32_t sbase = sb + st * GST;
        G_FRAGS(sbase, 0, 0);
#pragma unroll
        for (int ks = 0; ks < 4; ks++) {
            const int cur = ks & 1;
            if (ks < 3) G_FRAGS(sbase, cur ^ 1, ks + 1);
            mma_f16(acc[0][0], Af[cur][0], Bf[cur][0][0], Bf[cur][0][1]);
            mma_f16(acc[0][1], Af[cur][0], Bf[cur][0][2], Bf[cur][0][3]);
            mma_f16(acc[0][2], Af[cur][0], Bf[cur][1][0], Bf[cur][1][1]);
            mma_f16(acc[0][3], Af[cur][0], Bf[cur][1][2], Bf[cur][1][3]);
            mma_f16(acc[1][0], Af[cur][1], Bf[cur][0][0], Bf[cur][0][1]);
            mma_f16(acc[1][1], Af[cur][1], Bf[cur][0][2], Bf[cur][0][3]);
            mma_f16(acc[1][2], Af[cur][1], Bf[cur][1][0], Bf[cur][1][1]);
            mma_f16(acc[1][3], Af[cur][1], Bf[cur][1][2], Bf[cur][1][3]);
        }
    }

    // ---- epilogue: normalize + mish -> out ----
#pragma unroll
    for (int mt = 0; mt < 2; mt++) {
        const int lr = wm * 32 + mt * 16 + (lane >> 2);
        const float inv0 = __fdividef(1.f, denf[lr]);
        const float inv1 = __fdividef(1.f, denf[lr + 8]);
        float* o0 = out + (size_t)(row0 + lr) * FOUT + nbase;
        float* o1 = out + (size_t)(row0 + lr + 8) * FOUT + nbase;
#pragma unroll
        for (int nt = 0; nt < 4; nt++) {
            const int col = wn * 32 + nt * 8 + (lane & 3) * 2;
            float2 v0 = {fast_mish(acc[mt][nt][0] * inv0),
                         fast_mish(acc[mt][nt][1] * inv0)};
            float2 v1 = {fast_mish(acc[mt][nt][2] * inv1),
                         fast_mish(acc[mt][nt][3] * inv1)};
            *(float2*)&o0[col] = v0;
            *(float2*)&o1[col] = v1;
        }
    }
#undef G_PROD
#undef G_FRAGS
}

// ---------------------------------------------------------------------------
extern "C" void kernel_launch(void* const* d_in, const int* in_sizes, int n_in,
                              void* d_out, int out_size)
{
    const float* x   = (const float*)d_in[0];   // [8192, 512]
    const int*   adj = (const int*)  d_in[1];   // [8192, 8192]
    const float* w   = (const float*)d_in[2];   // [512, 256]
    const float* a   = (const float*)d_in[3];   // [512, 1]
    float* out = (float*)d_out;                 // [8192, 256]

    cudaFuncSetAttribute(k_xw_tc, cudaFuncAttributeMaxDynamicSharedMemorySize,
                         XT_SMEM);
    cudaFuncSetAttribute(k_gemm, cudaFuncAttributeMaxDynamicSharedMemorySize,
                         GEMM_SMEM);

    k_xw_tc<<<dim3(64, 2), 256, XT_SMEM>>>(x, w);    // launch 1
    k_scores<<<N_NODES / 8, 256>>>(a);               // launch 2
    k_wgen<<<N_NODES / 8, 256>>>(adj);               // launch 3
    k_gemm<<<dim3(128, 2), 256, GEMM_SMEM>>>(out);   // launch 4 (profiled)
}

// round 15
// speedup vs baseline: 1.2241x; 1.0287x over previous
#include <cuda_runtime.h>
#include <cuda_bf16.h>
#include <cuda_fp16.h>
#include <cstdint>

#define N_NODES 8192
#define FIN     512
#define FOUT    256
#define BKC     64                   // K-chunk
#define KHALF   (N_NODES / 2)        // 4096 per K-split CTA
#define NCHUNK_KS (KHALF / BKC)      // 64

// ---------------------------------------------------------------------------
// Device scratch
// ---------------------------------------------------------------------------
__device__ float g_h[(size_t)N_NODES * FOUT];          // 8 MB   h = x@W
__device__ float g_s[2 * N_NODES];                     // s_src | s_dst
__device__ float g_smax = -3.0e38f;                    // max_j s_dst (atomicMax)
__device__ __half g_hT[(size_t)FOUT * N_NODES];        // 4 MB   h^T fp16
__device__ __half g_w[(size_t)N_NODES * N_NODES];      // 128 MB weight matrix
__device__ float g_den[N_NODES];                       // row denominators
__device__ float g_pnum[2][(size_t)N_NODES * FOUT];    // 16 MB  K-split partials

// mish(u) = u*(t^2+2t)/(t^2+2t+2), t=e^u
__device__ __forceinline__ float fast_mish(float u) {
    if (u > 30.f) return u;
    float t = __expf(u);
    float v = t * (t + 2.f);
    return u * __fdividef(v, v + 2.f);
}
__device__ __forceinline__ uint32_t smem_u32(const void* p) {
    uint32_t a;
    asm("{ .reg .u64 t; cvta.to.shared.u64 t, %1; cvt.u32.u64 %0, t; }" : "=r"(a) : "l"(p));
    return a;
}
__device__ __forceinline__ void atomic_max_float(float* addr, float val) {
    int old = __float_as_int(*addr);
    while (__int_as_float(old) < val) {
        int prev = atomicCAS((int*)addr, old, __float_as_int(val));
        if (prev == old) break;
        old = prev;
    }
}
#define SW128(x) ((x) ^ (((x) >> 3) & 0x70))

// ---- baseline-PTX tensor / async ops (compute_103-safe) --------------------
__device__ __forceinline__ void ldsm4(uint32_t* r, uint32_t addr) {
    asm volatile("ldmatrix.sync.aligned.m8n8.x4.shared.b16 {%0,%1,%2,%3}, [%4];"
                 : "=r"(r[0]), "=r"(r[1]), "=r"(r[2]), "=r"(r[3]) : "r"(addr));
}
__device__ __forceinline__ void mma_f16(float* d, const uint32_t* a,
                                        uint32_t b0, uint32_t b1) {
    asm volatile("mma.sync.aligned.m16n8k16.row.col.f32.f16.f16.f32 "
                 "{%0,%1,%2,%3}, {%4,%5,%6,%7}, {%8,%9}, {%0,%1,%2,%3};"
                 : "+f"(d[0]), "+f"(d[1]), "+f"(d[2]), "+f"(d[3])
                 : "r"(a[0]), "r"(a[1]), "r"(a[2]), "r"(a[3]), "r"(b0), "r"(b1));
}
__device__ __forceinline__ void cpa16(uint32_t s, const void* g) {
    asm volatile("cp.async.cg.shared.global [%0], [%1], 16;" :: "r"(s), "l"(g));
}
#define CPA_COMMIT() asm volatile("cp.async.commit_group;" ::: "memory")
#define CPA_WAIT1()  asm volatile("cp.async.wait_group 1;" ::: "memory")
#define CPA_WAIT0()  asm volatile("cp.async.wait_group 0;" ::: "memory")

__device__ __forceinline__ uint32_t pack_hilo(float a, float b, uint32_t& lo) {
    __half ha = __float2half_rn(a), hb = __float2half_rn(b);
    __half la = __float2half_rn(a - __half2float(ha));
    __half lb = __float2half_rn(b - __half2float(hb));
    lo = (uint32_t)__half_as_ushort(la) | ((uint32_t)__half_as_ushort(lb) << 16);
    return (uint32_t)__half_as_ushort(ha) | ((uint32_t)__half_as_ushort(hb) << 16);
}

// ---------------------------------------------------------------------------
// Launch 1: h = x @ W via HMMA, 3-term fp16 hi/lo split; emits g_h + g_hT.
// ---------------------------------------------------------------------------
#define XT_AL 16384
#define XT_BH 32768
#define XT_BL 49152
#define XT_SMEM 65536

__global__ __launch_bounds__(256) void k_xw_tc(
    const float* __restrict__ X, const float* __restrict__ W)
{
    extern __shared__ char smem[];
    const uint32_t sb = smem_u32(smem);
    const int tid = threadIdx.x;
    const int lane = tid & 31;
    const int wid = tid >> 5;
    const int m0 = blockIdx.x * 128;
    const int n0 = blockIdx.y * 128;

    const int wm = wid & 3;
    const int wn = wid >> 2;
    const int ksw = lane & 7;
    const int alsel = lane >> 4;
    const int bg = lane >> 3;
    const int kb0 = bg & 1;
    const uint32_t arow  = (uint32_t)(wm * 32 + (lane & 15)) * 128;
    const uint32_t brow0 = XT_BH + (uint32_t)(wn * 64 + (lane & 7) + ((bg & 2) << 2)) * 128;

    float acc[2][8][4];
#pragma unroll
    for (int mt = 0; mt < 2; mt++)
#pragma unroll
        for (int nt = 0; nt < 8; nt++)
#pragma unroll
            for (int q = 0; q < 4; q++) acc[mt][nt][q] = 0.f;

    for (int c = 0; c < 8; c++) {
        const int k0 = c * 64;
        {
            const int row = tid >> 1, kh = tid & 1;
            const float4* xs = (const float4*)(X + (size_t)(m0 + row) * FIN + k0 + kh * 32);
#pragma unroll
            for (int i = 0; i < 8; i++) {
                float4 v = __ldg(xs + i);
                uint32_t l01, l23;
                uint32_t h01 = pack_hilo(v.x, v.y, l01);
                uint32_t h23 = pack_hilo(v.z, v.w, l23);
                uint32_t off = SW128((uint32_t)row * 128 + (kh * 32 + i * 4) * 2);
                *(uint2*)(smem + off) = make_uint2(h01, h23);
                *(uint2*)(smem + XT_AL + off) = make_uint2(l01, l23);
            }
        }
        {
            const int n = tid & 127, kh = tid >> 7;
#pragma unroll 8
            for (int kk = 0; kk < 32; kk++) {
                const int k = kh * 32 + kk;
                float v = __ldg(W + (size_t)(k0 + k) * FOUT + n0 + n);
                __half hv = __float2half_rn(v);
                __half lv = __float2half_rn(v - __half2float(hv));
                uint32_t off = SW128((uint32_t)n * 128 + k * 2);
                *(__half*)(smem + XT_BH + off) = hv;
                *(__half*)(smem + XT_BL + off) = lv;
            }
        }
        __syncthreads();

#pragma unroll
        for (int ks = 0; ks < 4; ks++) {
            uint32_t Ah[2][4], Al[2][4], Bh[4][4], Bl[4][4];
            const int kcA = ks * 2 + alsel;
            const uint32_t ao = (uint32_t)((kcA ^ ksw) << 4);
            ldsm4(Ah[0], sb + arow + ao);
            ldsm4(Ah[1], sb + arow + 2048 + ao);
            ldsm4(Al[0], sb + XT_AL + arow + ao);
            ldsm4(Al[1], sb + XT_AL + arow + 2048 + ao);
            const int kcB = ks * 2 + kb0;
            const uint32_t bo = (uint32_t)((kcB ^ ksw) << 4);
#pragma unroll
            for (int ng = 0; ng < 4; ng++) {
                ldsm4(Bh[ng], sb + brow0 + ng * 2048 + bo);
                ldsm4(Bl[ng], sb + brow0 + 16384 + ng * 2048 + bo);
            }
#pragma unroll
            for (int ng = 0; ng < 4; ng++) {
#pragma unroll
                for (int mt = 0; mt < 2; mt++) {
                    mma_f16(acc[mt][ng * 2],     Ah[mt], Bh[ng][0], Bh[ng][1]);
                    mma_f16(acc[mt][ng * 2 + 1], Ah[mt], Bh[ng][2], Bh[ng][3]);
                    mma_f16(acc[mt][ng * 2],     Al[mt], Bh[ng][0], Bh[ng][1]);
                    mma_f16(acc[mt][ng * 2 + 1], Al[mt], Bh[ng][2], Bh[ng][3]);
                    mma_f16(acc[mt][ng * 2],     Ah[mt], Bl[ng][0], Bl[ng][1]);
                    mma_f16(acc[mt][ng * 2 + 1], Ah[mt], Bl[ng][2], Bl[ng][3]);
                }
            }
        }
        __syncthreads();
    }

#pragma unroll
    for (int mt = 0; mt < 2; mt++) {
        const int lr = wm * 32 + mt * 16 + (lane >> 2);
#pragma unroll
        for (int nt = 0; nt < 8; nt++) {
            const int col = n0 + wn * 64 + nt * 8 + (lane & 3) * 2;
            float2 v0 = {acc[mt][nt][0], acc[mt][nt][1]};
            float2 v1 = {acc[mt][nt][2], acc[mt][nt][3]};
            *(float2*)&g_h[(size_t)(m0 + lr) * FOUT + col] = v0;
            *(float2*)&g_h[(size_t)(m0 + lr + 8) * FOUT + col] = v1;
        }
    }
    {
        __half* ht = (__half*)smem;     // [128][130]
#pragma unroll
        for (int mt = 0; mt < 2; mt++) {
            const int lr = wm * 32 + mt * 16 + (lane >> 2);
#pragma unroll
            for (int nt = 0; nt < 8; nt++) {
                const int col = wn * 64 + nt * 8 + (lane & 3) * 2;
                ht[lr * 130 + col]           = __float2half_rn(acc[mt][nt][0]);
                ht[lr * 130 + col + 1]       = __float2half_rn(acc[mt][nt][1]);
                ht[(lr + 8) * 130 + col]     = __float2half_rn(acc[mt][nt][2]);
                ht[(lr + 8) * 130 + col + 1] = __float2half_rn(acc[mt][nt][3]);
            }
        }
        __syncthreads();
#pragma unroll
        for (int i = tid; i < 16384; i += 256) {
            const int n = i >> 7, m = i & 127;
            g_hT[(size_t)(n0 + n) * N_NODES + m0 + m] = ht[m * 130 + n];
        }
    }
}

// ---------------------------------------------------------------------------
// Launch 2: s_src / s_dst + global max(s_dst)
// ---------------------------------------------------------------------------
__global__ __launch_bounds__(256) void k_scores(const float* __restrict__ A)
{
    const int row = blockIdx.x * 8 + (threadIdx.x >> 5);
    const int lane = threadIdx.x & 31;
    const float4* h4 = (const float4*)(g_h + (size_t)row * FOUT);
    const float4* a14 = (const float4*)A;
    const float4* a24 = (const float4*)(A + FOUT);
    float s1 = 0.f, s2 = 0.f;
#pragma unroll
    for (int i = 0; i < 2; i++) {
        int idx = lane + i * 32;
        float4 h = h4[idx], a1 = a14[idx], a2 = a24[idx];
        s1 += h.x * a1.x + h.y * a1.y + h.z * a1.z + h.w * a1.w;
        s2 += h.x * a2.x + h.y * a2.y + h.z * a2.z + h.w * a2.w;
    }
#pragma unroll
    for (int off = 16; off; off >>= 1) {
        s1 += __shfl_down_sync(0xffffffffu, s1, off);
        s2 += __shfl_down_sync(0xffffffffu, s2, off);
    }
    if (lane == 0) {
        g_s[row] = s1;
        g_s[N_NODES + row] = s2;
        atomic_max_float(&g_smax, s2);
    }
}

// ---------------------------------------------------------------------------
// Launch 3: W = exp(mish(s_i+s_j)-c_i) fp16 + row denominators (adj read raw).
// ---------------------------------------------------------------------------
__global__ __launch_bounds__(256) void k_wgen(const int* __restrict__ adj)
{
    const int lane = threadIdx.x & 31, wid = threadIdx.x >> 5;
    const int row = blockIdx.x * 8 + wid;
    const float ssrc = g_s[row];
    const float ci = fmaxf(ssrc + g_smax, 0.f);
    const float* __restrict__ sdst = g_s + N_NODES;
    const int4* __restrict__ arow = (const int4*)(adj + (size_t)row * N_NODES);
    __half* __restrict__ wrow = g_w + (size_t)row * N_NODES;
    float rsum = 0.f;
#pragma unroll 4
    for (int q = 0; q < 64; q++) {
        const int j4 = q * 32 + lane;
        int4   av = __ldg(arow + j4);
        float4 sv = __ldg((const float4*)sdst + j4);
        float w0 = (av.x > 0) ? __expf(fast_mish(ssrc + sv.x) - ci) : 0.f;
        float w1 = (av.y > 0) ? __expf(fast_mish(ssrc + sv.y) - ci) : 0.f;
        float w2 = (av.z > 0) ? __expf(fast_mish(ssrc + sv.z) - ci) : 0.f;
        float w3 = (av.w > 0) ? __expf(fast_mish(ssrc + sv.w) - ci) : 0.f;
        __half2 p01 = __floats2half2_rn(w0, w1);
        __half2 p23 = __floats2half2_rn(w2, w3);
        float2 f01 = __half22float2(p01);
        float2 f23 = __half22float2(p23);
        rsum += (f01.x + f01.y) + (f23.x + f23.y);
        uint2 pk = {*(uint32_t*)&p01, *(uint32_t*)&p23};
        *(uint2*)(wrow + j4 * 4) = pk;
    }
#pragma unroll
    for (int o = 16; o; o >>= 1) rsum += __shfl_down_sync(0xffffffffu, rsum, o);
    if (lane == 0) g_den[row] = rsum;
}

// ---------------------------------------------------------------------------
// Launch 4: fp16 GEMM partials  pnum[kh] = W[:, khalf] @ hT[:, khalf]^T.
// Grid (128, 2, 2) = 512 CTAs, 256 thr, 3 CTAs/SM (regs <= 85).
// CTA: M=64, N=128, K=4096. Warp 32x32. Single-buffered B frags.
// Stage (24KB x3): A 8K | B 16K. 3-stage cp.async, wait_group 1.
// ---------------------------------------------------------------------------
#define GST    24576
#define GOFF_B 8192
#define GEMM_SMEM (3 * GST)   // 73728; x3 CTAs = 216KB

__global__ __launch_bounds__(256, 3) void k_gemm()
{
    extern __shared__ char smem[];
    const uint32_t sb = smem_u32(smem);
    const int tid = threadIdx.x;
    const int lane = tid & 31;
    const int wid = tid >> 5;

    const int row0  = blockIdx.x * 64;
    const int nbase = blockIdx.y * 128;
    const int kh    = blockIdx.z;
    const int koff  = kh * KHALF;

    // cp.async mappings
    const int ar = tid >> 3;
    const uint32_t aoff = (uint32_t)(tid & 7) * 16;
    const char* __restrict__ asrc0 =
        (const char*)(g_w + (size_t)(row0 + ar) * N_NODES + koff) + aoff;
    const char* __restrict__ asrc1 =
        (const char*)(g_w + (size_t)(row0 + ar + 32) * N_NODES + koff) + aoff;
    const uint32_t adst0 = SW128((uint32_t)ar * 128 + aoff);
    const uint32_t adst1 = SW128((uint32_t)(ar + 32) * 128 + aoff);
    const int brow_p = tid & 127, bhalf = tid >> 7;
    const char* __restrict__ bsrc =
        (const char*)(g_hT + (size_t)(nbase + brow_p) * N_NODES + koff) + bhalf * 64;
    const uint32_t bb = (uint32_t)brow_p * 128 + bhalf * 64;

    // consumer mapping: warp (wm, wn): 32x32 tile
    const int wm = wid & 1;
    const int wn = wid >> 1;
    const int ksw = lane & 7;
    const int alsel = lane >> 4;
    const int bg = lane >> 3;
    const int kb0 = bg & 1;
    const uint32_t arow  = (uint32_t)(wm * 32 + (lane & 15)) * 128;
    const uint32_t brow0 = GOFF_B +
        (uint32_t)(wn * 32 + (lane & 7) + ((bg & 2) << 2)) * 128;

    float acc[2][4][4];
#pragma unroll
    for (int mt = 0; mt < 2; mt++)
#pragma unroll
        for (int nt = 0; nt < 4; nt++)
#pragma unroll
            for (int q = 0; q < 4; q++) acc[mt][nt][q] = 0.f;

    uint32_t Af[2][2][4];   // double-buffered A
    uint32_t Bf[2][4];      // single-buffered B

#define G_PROD(st_, c_)                                                          \
    {                                                                            \
        const uint32_t db = sb + (st_) * GST;                                    \
        cpa16(db + adst0, asrc0 + (size_t)(c_) * 128);                           \
        cpa16(db + adst1, asrc1 + (size_t)(c_) * 128);                           \
        const char* bs = bsrc + (size_t)(c_) * 128;                              \
        _Pragma("unroll")                                                        \
        for (int t = 0; t < 4; t++)                                              \
            cpa16(db + GOFF_B + SW128(bb + t * 16), bs + t * 16);                \
        CPA_COMMIT();                                                            \
    }

#define G_FRAGS_A(base_, buf_, ks_)                                              \
    {                                                                            \
        const int kcA = (ks_) * 2 + alsel;                                       \
        const uint32_t ao = (uint32_t)((kcA ^ ksw) << 4);                        \
        ldsm4(Af[buf_][0], (base_) + arow + ao);                                 \
        ldsm4(Af[buf_][1], (base_) + arow + 2048 + ao);                          \
    }
#define G_FRAGS_B(base_, ks_)                                                    \
    {                                                                            \
        const int kcB = (ks_) * 2 + kb0;                                         \
        const uint32_t bo = (uint32_t)((kcB ^ ksw) << 4);                        \
        ldsm4(Bf[0], (base_) + brow0 + bo);                                      \
        ldsm4(Bf[1], (base_) + brow0 + 2048 + bo);                               \
    }

    G_PROD(0, 0);
    G_PROD(1, 1);

    for (int c = 0; c < NCHUNK_KS; c++) {
        const int st = c % 3;
        if (c + 1 >= NCHUNK_KS) { CPA_WAIT0(); } else { CPA_WAIT1(); }
        __syncthreads();
        if (c + 2 < NCHUNK_KS) G_PROD((c + 2) % 3, c + 2);

        const uint32_t sbase = sb + st * GST;
        G_FRAGS_A(sbase, 0, 0);
#pragma unroll
        for (int ks = 0; ks < 4; ks++) {
            const int cur = ks & 1;
            G_FRAGS_B(sbase, ks);
            if (ks < 3) G_FRAGS_A(sbase, cur ^ 1, ks + 1);
            mma_f16(acc[0][0], Af[cur][0], Bf[0][0], Bf[0][1]);
            mma_f16(acc[0][1], Af[cur][0], Bf[0][2], Bf[0][3]);
            mma_f16(acc[0][2], Af[cur][0], Bf[1][0], Bf[1][1]);
            mma_f16(acc[0][3], Af[cur][0], Bf[1][2], Bf[1][3]);
            mma_f16(acc[1][0], Af[cur][1], Bf[0][0], Bf[0][1]);
            mma_f16(acc[1][1], Af[cur][1], Bf[0][2], Bf[0][3]);
            mma_f16(acc[1][2], Af[cur][1], Bf[1][0], Bf[1][1]);
            mma_f16(acc[1][3], Af[cur][1], Bf[1][2], Bf[1][3]);
        }
    }

    // ---- epilogue: raw fp32 partials ----
    float* base = g_pnum[kh];
#pragma unroll
    for (int mt = 0; mt < 2; mt++) {
        const int lr = wm * 32 + mt * 16 + (lane >> 2);
        float* o0 = base + (size_t)(row0 + lr) * FOUT + nbase;
        float* o1 = base + (size_t)(row0 + lr + 8) * FOUT + nbase;
#pragma unroll
        for (int nt = 0; nt < 4; nt++) {
            const int col = wn * 32 + nt * 8 + (lane & 3) * 2;
            float2 v0 = {acc[mt][nt][0], acc[mt][nt][1]};
            float2 v1 = {acc[mt][nt][2], acc[mt][nt][3]};
            *(float2*)&o0[col] = v0;
            *(float2*)&o1[col] = v1;
        }
    }
#undef G_PROD
#undef G_FRAGS_A
#undef G_FRAGS_B
}

// ---------------------------------------------------------------------------
// Launch 5: combine K-split partials + normalize + mish
// ---------------------------------------------------------------------------
__global__ __launch_bounds__(256) void k_combine(float* __restrict__ out)
{
    const int idx = blockIdx.x * 256 + threadIdx.x;       // float4 index
    const int row = idx >> 6;
    const float4* p0 = (const float4*)g_pnum[0];
    const float4* p1 = (const float4*)g_pnum[1];
    float inv = __fdividef(1.f, g_den[row]);
    float4 a = p0[idx], b = p1[idx];
    float4 o;
    o.x = fast_mish((a.x + b.x) * inv);
    o.y = fast_mish((a.y + b.y) * inv);
    o.z = fast_mish((a.z + b.z) * inv);
    o.w = fast_mish((a.w + b.w) * inv);
    ((float4*)out)[idx] = o;
}

// ---------------------------------------------------------------------------
extern "C" void kernel_launch(void* const* d_in, const int* in_sizes, int n_in,
                              void* d_out, int out_size)
{
    const float* x   = (const float*)d_in[0];   // [8192, 512]
    const int*   adj = (const int*)  d_in[1];   // [8192, 8192]
    const float* w   = (const float*)d_in[2];   // [512, 256]
    const float* a   = (const float*)d_in[3];   // [512, 1]
    float* out = (float*)d_out;                 // [8192, 256]

    cudaFuncSetAttribute(k_xw_tc, cudaFuncAttributeMaxDynamicSharedMemorySize,
                         XT_SMEM);
    cudaFuncSetAttribute(k_gemm, cudaFuncAttributeMaxDynamicSharedMemorySize,
                         GEMM_SMEM);

    k_xw_tc<<<dim3(64, 2), 256, XT_SMEM>>>(x, w);        // launch 1
    k_scores<<<N_NODES / 8, 256>>>(a);                   // launch 2
    k_wgen<<<N_NODES / 8, 256>>>(adj);                   // launch 3
    k_gemm<<<dim3(128, 2, 2), 256, GEMM_SMEM>>>();       // launch 4 (profiled)
    k_combine<<<(N_NODES * FOUT / 4) / 256, 256>>>(out); // launch 5
}

// round 16
// speedup vs baseline: 1.5145x; 1.2372x over previous
#include <cuda_runtime.h>
#include <cuda_bf16.h>
#include <cuda_fp16.h>
#include <cstdint>

#define N_NODES 8192
#define FIN     512
#define FOUT    256
#define BKC     64                   // K-chunk
#define NSPLIT  4
#define KQ      (N_NODES / NSPLIT)   // 2048 per K-split CTA
#define NCHUNK_KQ (KQ / BKC)         // 32

// ---------------------------------------------------------------------------
// Device scratch
// ---------------------------------------------------------------------------
__device__ float g_h[(size_t)N_NODES * FOUT];          // 8 MB   h = x@W
__device__ float g_s[2 * N_NODES];                     // s_src | s_dst
__device__ float g_smax = -3.0e38f;                    // max_j s_dst (atomicMax)
__device__ __half g_hT[(size_t)FOUT * N_NODES];        // 4 MB   h^T fp16
__device__ __half g_w[(size_t)N_NODES * N_NODES];      // 128 MB weight matrix
__device__ float g_den[N_NODES];                       // row denominators
__device__ float g_pnum[NSPLIT][(size_t)N_NODES * FOUT]; // 32 MB K-split partials

// mish(u) = u*(t^2+2t)/(t^2+2t+2), t=e^u
__device__ __forceinline__ float fast_mish(float u) {
    if (u > 30.f) return u;
    float t = __expf(u);
    float v = t * (t + 2.f);
    return u * __fdividef(v, v + 2.f);
}
__device__ __forceinline__ uint32_t smem_u32(const void* p) {
    uint32_t a;
    asm("{ .reg .u64 t; cvta.to.shared.u64 t, %1; cvt.u32.u64 %0, t; }" : "=r"(a) : "l"(p));
    return a;
}
__device__ __forceinline__ void atomic_max_float(float* addr, float val) {
    int old = __float_as_int(*addr);
    while (__int_as_float(old) < val) {
        int prev = atomicCAS((int*)addr, old, __float_as_int(val));
        if (prev == old) break;
        old = prev;
    }
}
#define SW128(x) ((x) ^ (((x) >> 3) & 0x70))

// ---- baseline-PTX tensor / async ops (compute_103-safe) --------------------
__device__ __forceinline__ void ldsm4(uint32_t* r, uint32_t addr) {
    asm volatile("ldmatrix.sync.aligned.m8n8.x4.shared.b16 {%0,%1,%2,%3}, [%4];"
                 : "=r"(r[0]), "=r"(r[1]), "=r"(r[2]), "=r"(r[3]) : "r"(addr));
}
__device__ __forceinline__ void mma_f16(float* d, const uint32_t* a,
                                        uint32_t b0, uint32_t b1) {
    asm volatile("mma.sync.aligned.m16n8k16.row.col.f32.f16.f16.f32 "
                 "{%0,%1,%2,%3}, {%4,%5,%6,%7}, {%8,%9}, {%0,%1,%2,%3};"
                 : "+f"(d[0]), "+f"(d[1]), "+f"(d[2]), "+f"(d[3])
                 : "r"(a[0]), "r"(a[1]), "r"(a[2]), "r"(a[3]), "r"(b0), "r"(b1));
}
__device__ __forceinline__ void cpa16(uint32_t s, const void* g) {
    asm volatile("cp.async.cg.shared.global [%0], [%1], 16;" :: "r"(s), "l"(g));
}
#define CPA_COMMIT() asm volatile("cp.async.commit_group;" ::: "memory")
#define CPA_WAIT1()  asm volatile("cp.async.wait_group 1;" ::: "memory")
#define CPA_WAIT0()  asm volatile("cp.async.wait_group 0;" ::: "memory")

__device__ __forceinline__ uint32_t pack_hilo(float a, float b, uint32_t& lo) {
    __half ha = __float2half_rn(a), hb = __float2half_rn(b);
    __half la = __float2half_rn(a - __half2float(ha));
    __half lb = __float2half_rn(b - __half2float(hb));
    lo = (uint32_t)__half_as_ushort(la) | ((uint32_t)__half_as_ushort(lb) << 16);
    return (uint32_t)__half_as_ushort(ha) | ((uint32_t)__half_as_ushort(hb) << 16);
}

// ---------------------------------------------------------------------------
// Launch 1: h = x @ W via HMMA, 3-term fp16 hi/lo split; emits g_h + g_hT.
// ---------------------------------------------------------------------------
#define XT_AL 16384
#define XT_BH 32768
#define XT_BL 49152
#define XT_SMEM 65536

__global__ __launch_bounds__(256) void k_xw_tc(
    const float* __restrict__ X, const float* __restrict__ W)
{
    extern __shared__ char smem[];
    const uint32_t sb = smem_u32(smem);
    const int tid = threadIdx.x;
    const int lane = tid & 31;
    const int wid = tid >> 5;
    const int m0 = blockIdx.x * 128;
    const int n0 = blockIdx.y * 128;

    const int wm = wid & 3;
    const int wn = wid >> 2;
    const int ksw = lane & 7;
    const int alsel = lane >> 4;
    const int bg = lane >> 3;
    const int kb0 = bg & 1;
    const uint32_t arow  = (uint32_t)(wm * 32 + (lane & 15)) * 128;
    const uint32_t brow0 = XT_BH + (uint32_t)(wn * 64 + (lane & 7) + ((bg & 2) << 2)) * 128;

    float acc[2][8][4];
#pragma unroll
    for (int mt = 0; mt < 2; mt++)
#pragma unroll
        for (int nt = 0; nt < 8; nt++)
#pragma unroll
            for (int q = 0; q < 4; q++) acc[mt][nt][q] = 0.f;

    for (int c = 0; c < 8; c++) {
        const int k0 = c * 64;
        {
            const int row = tid >> 1, kh = tid & 1;
            const float4* xs = (const float4*)(X + (size_t)(m0 + row) * FIN + k0 + kh * 32);
#pragma unroll
            for (int i = 0; i < 8; i++) {
                float4 v = __ldg(xs + i);
                uint32_t l01, l23;
                uint32_t h01 = pack_hilo(v.x, v.y, l01);
                uint32_t h23 = pack_hilo(v.z, v.w, l23);
                uint32_t off = SW128((uint32_t)row * 128 + (kh * 32 + i * 4) * 2);
                *(uint2*)(smem + off) = make_uint2(h01, h23);
                *(uint2*)(smem + XT_AL + off) = make_uint2(l01, l23);
            }
        }
        {
            const int n = tid & 127, kh = tid >> 7;
#pragma unroll 8
            for (int kk = 0; kk < 32; kk++) {
                const int k = kh * 32 + kk;
                float v = __ldg(W + (size_t)(k0 + k) * FOUT + n0 + n);
                __half hv = __float2half_rn(v);
                __half lv = __float2half_rn(v - __half2float(hv));
                uint32_t off = SW128((uint32_t)n * 128 + k * 2);
                *(__half*)(smem + XT_BH + off) = hv;
                *(__half*)(smem + XT_BL + off) = lv;
            }
        }
        __syncthreads();

#pragma unroll
        for (int ks = 0; ks < 4; ks++) {
            uint32_t Ah[2][4], Al[2][4], Bh[4][4], Bl[4][4];
            const int kcA = ks * 2 + alsel;
            const uint32_t ao = (uint32_t)((kcA ^ ksw) << 4);
            ldsm4(Ah[0], sb + arow + ao);
            ldsm4(Ah[1], sb + arow + 2048 + ao);
            ldsm4(Al[0], sb + XT_AL + arow + ao);
            ldsm4(Al[1], sb + XT_AL + arow + 2048 + ao);
            const int kcB = ks * 2 + kb0;
            const uint32_t bo = (uint32_t)((kcB ^ ksw) << 4);
#pragma unroll
            for (int ng = 0; ng < 4; ng++) {
                ldsm4(Bh[ng], sb + brow0 + ng * 2048 + bo);
                ldsm4(Bl[ng], sb + brow0 + 16384 + ng * 2048 + bo);
            }
#pragma unroll
            for (int ng = 0; ng < 4; ng++) {
#pragma unroll
                for (int mt = 0; mt < 2; mt++) {
                    mma_f16(acc[mt][ng * 2],     Ah[mt], Bh[ng][0], Bh[ng][1]);
                    mma_f16(acc[mt][ng * 2 + 1], Ah[mt], Bh[ng][2], Bh[ng][3]);
                    mma_f16(acc[mt][ng * 2],     Al[mt], Bh[ng][0], Bh[ng][1]);
                    mma_f16(acc[mt][ng * 2 + 1], Al[mt], Bh[ng][2], Bh[ng][3]);
                    mma_f16(acc[mt][ng * 2],     Ah[mt], Bl[ng][0], Bl[ng][1]);
                    mma_f16(acc[mt][ng * 2 + 1], Ah[mt], Bl[ng][2], Bl[ng][3]);
                }
            }
        }
        __syncthreads();
    }

#pragma unroll
    for (int mt = 0; mt < 2; mt++) {
        const int lr = wm * 32 + mt * 16 + (lane >> 2);
#pragma unroll
        for (int nt = 0; nt < 8; nt++) {
            const int col = n0 + wn * 64 + nt * 8 + (lane & 3) * 2;
            float2 v0 = {acc[mt][nt][0], acc[mt][nt][1]};
            float2 v1 = {acc[mt][nt][2], acc[mt][nt][3]};
            *(float2*)&g_h[(size_t)(m0 + lr) * FOUT + col] = v0;
            *(float2*)&g_h[(size_t)(m0 + lr + 8) * FOUT + col] = v1;
        }
    }
    {
        __half* ht = (__half*)smem;     // [128][130]
#pragma unroll
        for (int mt = 0; mt < 2; mt++) {
            const int lr = wm * 32 + mt * 16 + (lane >> 2);
#pragma unroll
            for (int nt = 0; nt < 8; nt++) {
                const int col = wn * 64 + nt * 8 + (lane & 3) * 2;
                ht[lr * 130 + col]           = __float2half_rn(acc[mt][nt][0]);
                ht[lr * 130 + col + 1]       = __float2half_rn(acc[mt][nt][1]);
                ht[(lr + 8) * 130 + col]     = __float2half_rn(acc[mt][nt][2]);
                ht[(lr + 8) * 130 + col + 1] = __float2half_rn(acc[mt][nt][3]);
            }
        }
        __syncthreads();
#pragma unroll
        for (int i = tid; i < 16384; i += 256) {
            const int n = i >> 7, m = i & 127;
            g_hT[(size_t)(n0 + n) * N_NODES + m0 + m] = ht[m * 130 + n];
        }
    }
}

// ---------------------------------------------------------------------------
// Launch 2: s_src / s_dst + global max(s_dst)
// ---------------------------------------------------------------------------
__global__ __launch_bounds__(256) void k_scores(const float* __restrict__ A)
{
    const int row = blockIdx.x * 8 + (threadIdx.x >> 5);
    const int lane = threadIdx.x & 31;
    const float4* h4 = (const float4*)(g_h + (size_t)row * FOUT);
    const float4* a14 = (const float4*)A;
    const float4* a24 = (const float4*)(A + FOUT);
    float s1 = 0.f, s2 = 0.f;
#pragma unroll
    for (int i = 0; i < 2; i++) {
        int idx = lane + i * 32;
        float4 h = h4[idx], a1 = a14[idx], a2 = a24[idx];
        s1 += h.x * a1.x + h.y * a1.y + h.z * a1.z + h.w * a1.w;
        s2 += h.x * a2.x + h.y * a2.y + h.z * a2.z + h.w * a2.w;
    }
#pragma unroll
    for (int off = 16; off; off >>= 1) {
        s1 += __shfl_down_sync(0xffffffffu, s1, off);
        s2 += __shfl_down_sync(0xffffffffu, s2, off);
    }
    if (lane == 0) {
        g_s[row] = s1;
        g_s[N_NODES + row] = s2;
        atomic_max_float(&g_smax, s2);
    }
}

// ---------------------------------------------------------------------------
// Launch 3: W = exp(mish(s_i+s_j)-c_i) fp16 + row denominators (adj read raw).
// ---------------------------------------------------------------------------
__global__ __launch_bounds__(256) void k_wgen(const int* __restrict__ adj)
{
    const int lane = threadIdx.x & 31, wid = threadIdx.x >> 5;
    const int row = blockIdx.x * 8 + wid;
    const float ssrc = g_s[row];
    const float ci = fmaxf(ssrc + g_smax, 0.f);
    const float* __restrict__ sdst = g_s + N_NODES;
    const int4* __restrict__ arow = (const int4*)(adj + (size_t)row * N_NODES);
    __half* __restrict__ wrow = g_w + (size_t)row * N_NODES;
    float rsum = 0.f;
#pragma unroll 4
    for (int q = 0; q < 64; q++) {
        const int j4 = q * 32 + lane;
        int4   av = __ldg(arow + j4);
        float4 sv = __ldg((const float4*)sdst + j4);
        float w0 = (av.x > 0) ? __expf(fast_mish(ssrc + sv.x) - ci) : 0.f;
        float w1 = (av.y > 0) ? __expf(fast_mish(ssrc + sv.y) - ci) : 0.f;
        float w2 = (av.z > 0) ? __expf(fast_mish(ssrc + sv.z) - ci) : 0.f;
        float w3 = (av.w > 0) ? __expf(fast_mish(ssrc + sv.w) - ci) : 0.f;
        __half2 p01 = __floats2half2_rn(w0, w1);
        __half2 p23 = __floats2half2_rn(w2, w3);
        float2 f01 = __half22float2(p01);
        float2 f23 = __half22float2(p23);
        rsum += (f01.x + f01.y) + (f23.x + f23.y);
        uint2 pk = {*(uint32_t*)&p01, *(uint32_t*)&p23};
        *(uint2*)(wrow + j4 * 4) = pk;
    }
#pragma unroll
    for (int o = 16; o; o >>= 1) rsum += __shfl_down_sync(0xffffffffu, rsum, o);
    if (lane == 0) g_den[row] = rsum;
}

// ---------------------------------------------------------------------------
// Launch 4: fp16 GEMM partials  pnum[kq] = W[:, kq] @ hT[:, kq]^T.
// Grid (64, 2, 4) = 512 CTAs, 256 thr, 2 CTAs/SM.
// CTA: M=128, N=128, K=2048 (32 chunks). 8 warps 2m x 4n, warp tile 64x32
// -> 192 B LDSM per HMMA (-25% smem traffic vs 32x32).
// Stage (32KB x3): A [128x64] 16K | B [128x64] 16K. cp.async wait_group 1.
// ---------------------------------------------------------------------------
#define GST    32768
#define GOFF_B 16384
#define GEMM_SMEM (3 * GST)   // 98304; x2 CTAs = 196608

__global__ __launch_bounds__(256, 2) void k_gemm()
{
    extern __shared__ char smem[];
    const uint32_t sb = smem_u32(smem);
    const int tid = threadIdx.x;
    const int lane = tid & 31;
    const int wid = tid >> 5;

    const int row0  = blockIdx.x * 128;
    const int nbase = blockIdx.y * 128;
    const int kq    = blockIdx.z;
    const int koff  = kq * KQ;

    // cp.async mappings: thread -> row tid>>1, 64B half (tid&1); A and B same shape
    const int pr = tid >> 1;
    const uint32_t poff = (uint32_t)(tid & 1) * 64;
    const char* __restrict__ asrc =
        (const char*)(g_w + (size_t)(row0 + pr) * N_NODES + koff) + poff;
    const char* __restrict__ bsrc =
        (const char*)(g_hT + (size_t)(nbase + pr) * N_NODES + koff) + poff;
    const uint32_t pb = (uint32_t)pr * 128 + poff;

    // consumer mapping: warp (wm, wn): 64x32 tile
    const int wm = wid & 1;
    const int wn = wid >> 1;            // 0..3
    const int ksw = lane & 7;
    const int alsel = lane >> 4;
    const int bg = lane >> 3;
    const int kb0 = bg & 1;
    const uint32_t arow  = (uint32_t)(wm * 64 + (lane & 15)) * 128;
    const uint32_t brow0 = GOFF_B +
        (uint32_t)(wn * 32 + (lane & 7) + ((bg & 2) << 2)) * 128;

    float acc[4][4][4];
#pragma unroll
    for (int mt = 0; mt < 4; mt++)
#pragma unroll
        for (int nt = 0; nt < 4; nt++)
#pragma unroll
            for (int q = 0; q < 4; q++) acc[mt][nt][q] = 0.f;

    uint32_t Af[4][4];
    uint32_t Bf[2][4];

#define G_PROD(st_, c_)                                                          \
    {                                                                            \
        const uint32_t db = sb + (st_) * GST;                                    \
        const char* as = asrc + (size_t)(c_) * 128;                              \
        const char* bs = bsrc + (size_t)(c_) * 128;                              \
        _Pragma("unroll")                                                        \
        for (int t = 0; t < 4; t++) {                                            \
            uint32_t so = SW128(pb + t * 16);                                    \
            cpa16(db + so, as + t * 16);                                         \
            cpa16(db + GOFF_B + so, bs + t * 16);                                \
        }                                                                        \
        CPA_COMMIT();                                                            \
    }

    G_PROD(0, 0);
    G_PROD(1, 1);

    for (int c = 0; c < NCHUNK_KQ; c++) {
        const int st = c % 3;
        if (c + 1 >= NCHUNK_KQ) { CPA_WAIT0(); } else { CPA_WAIT1(); }
        __syncthreads();
        if (c + 2 < NCHUNK_KQ) G_PROD((c + 2) % 3, c + 2);

        const uint32_t sbase = sb + st * GST;
#pragma unroll
        for (int ks = 0; ks < 4; ks++) {
            // A: 4 m16 frags (16 rows = 2048 B apart)
            const int kcA = ks * 2 + alsel;
            const uint32_t ao = (uint32_t)((kcA ^ ksw) << 4);
            ldsm4(Af[0], sbase + arow + ao);
            ldsm4(Af[1], sbase + arow + 2048 + ao);
            ldsm4(Af[2], sbase + arow + 4096 + ao);
            ldsm4(Af[3], sbase + arow + 6144 + ao);
            // B: 2 ldsm = 4 n8 slices
            const int kcB = ks * 2 + kb0;
            const uint32_t bo = (uint32_t)((kcB ^ ksw) << 4);
            ldsm4(Bf[0], sbase + brow0 + bo);
            ldsm4(Bf[1], sbase + brow0 + 2048 + bo);
            // 16 HMMAs, all-distinct accumulators
#pragma unroll
            for (int mt = 0; mt < 4; mt++) {
                mma_f16(acc[mt][0], Af[mt], Bf[0][0], Bf[0][1]);
                mma_f16(acc[mt][1], Af[mt], Bf[0][2], Bf[0][3]);
                mma_f16(acc[mt][2], Af[mt], Bf[1][0], Bf[1][1]);
                mma_f16(acc[mt][3], Af[mt], Bf[1][2], Bf[1][3]);
            }
        }
    }

    // ---- epilogue: raw fp32 partials ----
    float* base = g_pnum[kq];
#pragma unroll
    for (int mt = 0; mt < 4; mt++) {
        const int lr = wm * 64 + mt * 16 + (lane >> 2);
        float* o0 = base + (size_t)(row0 + lr) * FOUT + nbase;
        float* o1 = base + (size_t)(row0 + lr + 8) * FOUT + nbase;
#pragma unroll
        for (int nt = 0; nt < 4; nt++) {
            const int col = wn * 32 + nt * 8 + (lane & 3) * 2;
            float2 v0 = {acc[mt][nt][0], acc[mt][nt][1]};
            float2 v1 = {acc[mt][nt][2], acc[mt][nt][3]};
            *(float2*)&o0[col] = v0;
            *(float2*)&o1[col] = v1;
        }
    }
#undef G_PROD
}

// ---------------------------------------------------------------------------
// Launch 5: combine K-split partials + normalize + mish
// ---------------------------------------------------------------------------
__global__ __launch_bounds__(256) void k_combine(float* __restrict__ out)
{
    const int idx = blockIdx.x * 256 + threadIdx.x;       // float4 index
    const int row = idx >> 6;
    const float4* p0 = (const float4*)g_pnum[0];
    const float4* p1 = (const float4*)g_pnum[1];
    const float4* p2 = (const float4*)g_pnum[2];
    const float4* p3 = (const float4*)g_pnum[3];
    float inv = __fdividef(1.f, g_den[row]);
    float4 a = p0[idx], b = p1[idx], c = p2[idx], d = p3[idx];
    float4 o;
    o.x = fast_mish(((a.x + b.x) + (c.x + d.x)) * inv);
    o.y = fast_mish(((a.y + b.y) + (c.y + d.y)) * inv);
    o.z = fast_mish(((a.z + b.z) + (c.z + d.z)) * inv);
    o.w = fast_mish(((a.w + b.w) + (c.w + d.w)) * inv);
    ((float4*)out)[idx] = o;
}

// ---------------------------------------------------------------------------
extern "C" void kernel_launch(void* const* d_in, const int* in_sizes, int n_in,
                              void* d_out, int out_size)
{
    const float* x   = (const float*)d_in[0];   // [8192, 512]
    const int*   adj = (const int*)  d_in[1];   // [8192, 8192]
    const float* w   = (const float*)d_in[2];   // [512, 256]
    const float* a   = (const float*)d_in[3];   // [512, 1]
    float* out = (float*)d_out;                 // [8192, 256]

    cudaFuncSetAttribute(k_xw_tc, cudaFuncAttributeMaxDynamicSharedMemorySize,
                         XT_SMEM);
    cudaFuncSetAttribute(k_gemm, cudaFuncAttributeMaxDynamicSharedMemorySize,
                         GEMM_SMEM);

    k_xw_tc<<<dim3(64, 2), 256, XT_SMEM>>>(x, w);        // launch 1
    k_scores<<<N_NODES / 8, 256>>>(a);                   // launch 2
    k_wgen<<<N_NODES / 8, 256>>>(adj);                   // launch 3
    k_gemm<<<dim3(64, 2, NSPLIT), 256, GEMM_SMEM>>>();   // launch 4 (profiled)
    k_combine<<<(N_NODES * FOUT / 4) / 256, 256>>>(out); // launch 5
}

// round 17
// speedup vs baseline: 1.5516x; 1.0245x over previous
#include <cuda_runtime.h>
#include <cuda_bf16.h>
#include <cuda_fp16.h>
#include <cstdint>

#define N_NODES 8192
#define FIN     512
#define FOUT    256
#define BKC     64                   // K-chunk
#define NSPLIT  4
#define KQ      (N_NODES / NSPLIT)   // 2048 per K-split CTA
#define NCHUNK_KQ (KQ / BKC)         // 32

// ---------------------------------------------------------------------------
// Device scratch
// ---------------------------------------------------------------------------
__device__ float g_wa1[FIN];                           // W @ a1
__device__ float g_wa2[FIN];                           // W @ a2
__device__ float g_s[2 * N_NODES];                     // s_src | s_dst
__device__ float g_smax = -3.0e38f;                    // max_j s_dst (atomicMax)
__device__ __half g_hT[(size_t)FOUT * N_NODES];        // 4 MB   h^T fp16
__device__ __half g_w[(size_t)N_NODES * N_NODES];      // 128 MB weight matrix
__device__ float g_den[N_NODES];                       // row denominators
__device__ float g_pnum[NSPLIT][(size_t)N_NODES * FOUT]; // 32 MB K-split partials

// mish(u) = u*(t^2+2t)/(t^2+2t+2), t=e^u
__device__ __forceinline__ float fast_mish(float u) {
    if (u > 30.f) return u;
    float t = __expf(u);
    float v = t * (t + 2.f);
    return u * __fdividef(v, v + 2.f);
}
__device__ __forceinline__ uint32_t smem_u32(const void* p) {
    uint32_t a;
    asm("{ .reg .u64 t; cvta.to.shared.u64 t, %1; cvt.u32.u64 %0, t; }" : "=r"(a) : "l"(p));
    return a;
}
__device__ __forceinline__ void atomic_max_float(float* addr, float val) {
    int old = __float_as_int(*addr);
    while (__int_as_float(old) < val) {
        int prev = atomicCAS((int*)addr, old, __float_as_int(val));
        if (prev == old) break;
        old = prev;
    }
}
#define SW128(x) ((x) ^ (((x) >> 3) & 0x70))

// ---- baseline-PTX tensor / async ops (compute_103-safe) --------------------
__device__ __forceinline__ void ldsm4(uint32_t* r, uint32_t addr) {
    asm volatile("ldmatrix.sync.aligned.m8n8.x4.shared.b16 {%0,%1,%2,%3}, [%4];"
                 : "=r"(r[0]), "=r"(r[1]), "=r"(r[2]), "=r"(r[3]) : "r"(addr));
}
__device__ __forceinline__ void mma_f16(float* d, const uint32_t* a,
                                        uint32_t b0, uint32_t b1) {
    asm volatile("mma.sync.aligned.m16n8k16.row.col.f32.f16.f16.f32 "
                 "{%0,%1,%2,%3}, {%4,%5,%6,%7}, {%8,%9}, {%0,%1,%2,%3};"
                 : "+f"(d[0]), "+f"(d[1]), "+f"(d[2]), "+f"(d[3])
                 : "r"(a[0]), "r"(a[1]), "r"(a[2]), "r"(a[3]), "r"(b0), "r"(b1));
}
__device__ __forceinline__ void cpa16(uint32_t s, const void* g) {
    asm volatile("cp.async.cg.shared.global [%0], [%1], 16;" :: "r"(s), "l"(g));
}
#define CPA_COMMIT() asm volatile("cp.async.commit_group;" ::: "memory")
#define CPA_WAIT1()  asm volatile("cp.async.wait_group 1;" ::: "memory")
#define CPA_WAIT0()  asm volatile("cp.async.wait_group 0;" ::: "memory")

__device__ __forceinline__ uint32_t pack_hilo(float a, float b, uint32_t& lo) {
    __half ha = __float2half_rn(a), hb = __float2half_rn(b);
    __half la = __float2half_rn(a - __half2float(ha));
    __half lb = __float2half_rn(b - __half2float(hb));
    lo = (uint32_t)__half_as_ushort(la) | ((uint32_t)__half_as_ushort(lb) << 16);
    return (uint32_t)__half_as_ushort(ha) | ((uint32_t)__half_as_ushort(hb) << 16);
}

// ---------------------------------------------------------------------------
// k_wa: wa1 = W @ a[:256], wa2 = W @ a[256:]. One warp per W row.
// ---------------------------------------------------------------------------
__global__ __launch_bounds__(256) void k_wa(
    const float* __restrict__ W, const float* __restrict__ A)
{
    const int k = blockIdx.x * 8 + (threadIdx.x >> 5);
    const int lane = threadIdx.x & 31;
    const float4* wr = (const float4*)(W + (size_t)k * FOUT);
    const float4* a14 = (const float4*)A;
    const float4* a24 = (const float4*)(A + FOUT);
    float s1 = 0.f, s2 = 0.f;
#pragma unroll
    for (int i = 0; i < 2; i++) {
        int idx = lane + i * 32;
        float4 w = wr[idx], a1 = a14[idx], a2 = a24[idx];
        s1 += w.x * a1.x + w.y * a1.y + w.z * a1.z + w.w * a1.w;
        s2 += w.x * a2.x + w.y * a2.y + w.z * a2.z + w.w * a2.w;
    }
#pragma unroll
    for (int o = 16; o; o >>= 1) {
        s1 += __shfl_down_sync(0xffffffffu, s1, o);
        s2 += __shfl_down_sync(0xffffffffu, s2, o);
    }
    if (lane == 0) { g_wa1[k] = s1; g_wa2[k] = s2; }
}

// ---------------------------------------------------------------------------
// k_scores_x: s_src[i] = x[i,:].wa1, s_dst[i] = x[i,:].wa2 + smax atomic.
// One warp per row.
// ---------------------------------------------------------------------------
__global__ __launch_bounds__(256) void k_scores_x(const float* __restrict__ X)
{
    const int row = blockIdx.x * 8 + (threadIdx.x >> 5);
    const int lane = threadIdx.x & 31;
    const float4* xr = (const float4*)(X + (size_t)row * FIN);
    const float4* w14 = (const float4*)g_wa1;
    const float4* w24 = (const float4*)g_wa2;
    float s1 = 0.f, s2 = 0.f;
#pragma unroll
    for (int i = 0; i < 4; i++) {
        int idx = lane + i * 32;
        float4 xv = xr[idx], w1 = w14[idx], w2 = w24[idx];
        s1 += xv.x * w1.x + xv.y * w1.y + xv.z * w1.z + xv.w * w1.w;
        s2 += xv.x * w2.x + xv.y * w2.y + xv.z * w2.z + xv.w * w2.w;
    }
#pragma unroll
    for (int o = 16; o; o >>= 1) {
        s1 += __shfl_down_sync(0xffffffffu, s1, o);
        s2 += __shfl_down_sync(0xffffffffu, s2, o);
    }
    if (lane == 0) {
        g_s[row] = s1;
        g_s[N_NODES + row] = s2;
        atomic_max_float(&g_smax, s2);
    }
}

// ---------------------------------------------------------------------------
// k_xw_tc: h^T fp16 = (x @ W)^T via HMMA 3-term fp16 hi/lo split. (side stream)
// ---------------------------------------------------------------------------
#define XT_AL 16384
#define XT_BH 32768
#define XT_BL 49152
#define XT_SMEM 65536

__global__ __launch_bounds__(256) void k_xw_tc(
    const float* __restrict__ X, const float* __restrict__ W)
{
    extern __shared__ char smem[];
    const uint32_t sb = smem_u32(smem);
    const int tid = threadIdx.x;
    const int lane = tid & 31;
    const int wid = tid >> 5;
    const int m0 = blockIdx.x * 128;
    const int n0 = blockIdx.y * 128;

    const int wm = wid & 3;
    const int wn = wid >> 2;
    const int ksw = lane & 7;
    const int alsel = lane >> 4;
    const int bg = lane >> 3;
    const int kb0 = bg & 1;
    const uint32_t arow  = (uint32_t)(wm * 32 + (lane & 15)) * 128;
    const uint32_t brow0 = XT_BH + (uint32_t)(wn * 64 + (lane & 7) + ((bg & 2) << 2)) * 128;

    float acc[2][8][4];
#pragma unroll
    for (int mt = 0; mt < 2; mt++)
#pragma unroll
        for (int nt = 0; nt < 8; nt++)
#pragma unroll
            for (int q = 0; q < 4; q++) acc[mt][nt][q] = 0.f;

    for (int c = 0; c < 8; c++) {
        const int k0 = c * 64;
        {
            const int row = tid >> 1, kh = tid & 1;
            const float4* xs = (const float4*)(X + (size_t)(m0 + row) * FIN + k0 + kh * 32);
#pragma unroll
            for (int i = 0; i < 8; i++) {
                float4 v = __ldg(xs + i);
                uint32_t l01, l23;
                uint32_t h01 = pack_hilo(v.x, v.y, l01);
                uint32_t h23 = pack_hilo(v.z, v.w, l23);
                uint32_t off = SW128((uint32_t)row * 128 + (kh * 32 + i * 4) * 2);
                *(uint2*)(smem + off) = make_uint2(h01, h23);
                *(uint2*)(smem + XT_AL + off) = make_uint2(l01, l23);
            }
        }
        {
            const int n = tid & 127, kh = tid >> 7;
#pragma unroll 8
            for (int kk = 0; kk < 32; kk++) {
                const int k = kh * 32 + kk;
                float v = __ldg(W + (size_t)(k0 + k) * FOUT + n0 + n);
                __half hv = __float2half_rn(v);
                __half lv = __float2half_rn(v - __half2float(hv));
                uint32_t off = SW128((uint32_t)n * 128 + k * 2);
                *(__half*)(smem + XT_BH + off) = hv;
                *(__half*)(smem + XT_BL + off) = lv;
            }
        }
        __syncthreads();

#pragma unroll
        for (int ks = 0; ks < 4; ks++) {
            uint32_t Ah[2][4], Al[2][4], Bh[4][4], Bl[4][4];
            const int kcA = ks * 2 + alsel;
            const uint32_t ao = (uint32_t)((kcA ^ ksw) << 4);
            ldsm4(Ah[0], sb + arow + ao);
            ldsm4(Ah[1], sb + arow + 2048 + ao);
            ldsm4(Al[0], sb + XT_AL + arow + ao);
            ldsm4(Al[1], sb + XT_AL + arow + 2048 + ao);
            const int kcB = ks * 2 + kb0;
            const uint32_t bo = (uint32_t)((kcB ^ ksw) << 4);
#pragma unroll
            for (int ng = 0; ng < 4; ng++) {
                ldsm4(Bh[ng], sb + brow0 + ng * 2048 + bo);
                ldsm4(Bl[ng], sb + brow0 + 16384 + ng * 2048 + bo);
            }
#pragma unroll
            for (int ng = 0; ng < 4; ng++) {
#pragma unroll
                for (int mt = 0; mt < 2; mt++) {
                    mma_f16(acc[mt][ng * 2],     Ah[mt], Bh[ng][0], Bh[ng][1]);
                    mma_f16(acc[mt][ng * 2 + 1], Ah[mt], Bh[ng][2], Bh[ng][3]);
                    mma_f16(acc[mt][ng * 2],     Al[mt], Bh[ng][0], Bh[ng][1]);
                    mma_f16(acc[mt][ng * 2 + 1], Al[mt], Bh[ng][2], Bh[ng][3]);
                    mma_f16(acc[mt][ng * 2],     Ah[mt], Bl[ng][0], Bl[ng][1]);
                    mma_f16(acc[mt][ng * 2 + 1], Ah[mt], Bl[ng][2], Bl[ng][3]);
                }
            }
        }
        __syncthreads();
    }

    // epilogue: g_hT fp16 via smem transpose (g_h no longer exists)
    {
        __half* ht = (__half*)smem;     // [128][130]
#pragma unroll
        for (int mt = 0; mt < 2; mt++) {
            const int lr = wm * 32 + mt * 16 + (lane >> 2);
#pragma unroll
            for (int nt = 0; nt < 8; nt++) {
                const int col = wn * 64 + nt * 8 + (lane & 3) * 2;
                ht[lr * 130 + col]           = __float2half_rn(acc[mt][nt][0]);
                ht[lr * 130 + col + 1]       = __float2half_rn(acc[mt][nt][1]);
                ht[(lr + 8) * 130 + col]     = __float2half_rn(acc[mt][nt][2]);
                ht[(lr + 8) * 130 + col + 1] = __float2half_rn(acc[mt][nt][3]);
            }
        }
        __syncthreads();
#pragma unroll
        for (int i = tid; i < 16384; i += 256) {
            const int n = i >> 7, m = i & 127;
            g_hT[(size_t)(n0 + n) * N_NODES + m0 + m] = ht[m * 130 + n];
        }
    }
}

// ---------------------------------------------------------------------------
// k_wgen: W = exp(mish(s_i+s_j)-c_i) fp16 + row denominators (adj read raw).
// ---------------------------------------------------------------------------
__global__ __launch_bounds__(256) void k_wgen(const int* __restrict__ adj)
{
    const int lane = threadIdx.x & 31, wid = threadIdx.x >> 5;
    const int row = blockIdx.x * 8 + wid;
    const float ssrc = g_s[row];
    const float ci = fmaxf(ssrc + g_smax, 0.f);
    const float* __restrict__ sdst = g_s + N_NODES;
    const int4* __restrict__ arow = (const int4*)(adj + (size_t)row * N_NODES);
    __half* __restrict__ wrow = g_w + (size_t)row * N_NODES;
    float rsum = 0.f;
#pragma unroll 4
    for (int q = 0; q < 64; q++) {
        const int j4 = q * 32 + lane;
        int4   av = __ldg(arow + j4);
        float4 sv = __ldg((const float4*)sdst + j4);
        float w0 = (av.x > 0) ? __expf(fast_mish(ssrc + sv.x) - ci) : 0.f;
        float w1 = (av.y > 0) ? __expf(fast_mish(ssrc + sv.y) - ci) : 0.f;
        float w2 = (av.z > 0) ? __expf(fast_mish(ssrc + sv.z) - ci) : 0.f;
        float w3 = (av.w > 0) ? __expf(fast_mish(ssrc + sv.w) - ci) : 0.f;
        __half2 p01 = __floats2half2_rn(w0, w1);
        __half2 p23 = __floats2half2_rn(w2, w3);
        float2 f01 = __half22float2(p01);
        float2 f23 = __half22float2(p23);
        rsum += (f01.x + f01.y) + (f23.x + f23.y);
        uint2 pk = {*(uint32_t*)&p01, *(uint32_t*)&p23};
        *(uint2*)(wrow + j4 * 4) = pk;
    }
#pragma unroll
    for (int o = 16; o; o >>= 1) rsum += __shfl_down_sync(0xffffffffu, rsum, o);
    if (lane == 0) g_den[row] = rsum;
}

// ---------------------------------------------------------------------------
// k_gemm: fp16 GEMM partials  pnum[kq] = W[:, kq] @ hT[:, kq]^T.  [R16 config]
// Grid (64, 2, 4) = 512 CTAs, 256 thr, 2 CTAs/SM.
// CTA: M=128, N=128, K=2048 (32 chunks). 8 warps 2m x 4n, warp tile 64x32.
// ---------------------------------------------------------------------------
#define GST    32768
#define GOFF_B 16384
#define GEMM_SMEM (3 * GST)   // 98304; x2 CTAs = 196608

__global__ __launch_bounds__(256, 2) void k_gemm()
{
    extern __shared__ char smem[];
    const uint32_t sb = smem_u32(smem);
    const int tid = threadIdx.x;
    const int lane = tid & 31;
    const int wid = tid >> 5;

    const int row0  = blockIdx.x * 128;
    const int nbase = blockIdx.y * 128;
    const int kq    = blockIdx.z;
    const int koff  = kq * KQ;

    const int pr = tid >> 1;
    const uint32_t poff = (uint32_t)(tid & 1) * 64;
    const char* __restrict__ asrc =
        (const char*)(g_w + (size_t)(row0 + pr) * N_NODES + koff) + poff;
    const char* __restrict__ bsrc =
        (const char*)(g_hT + (size_t)(nbase + pr) * N_NODES + koff) + poff;
    const uint32_t pb = (uint32_t)pr * 128 + poff;

    const int wm = wid & 1;
    const int wn = wid >> 1;
    const int ksw = lane & 7;
    const int alsel = lane >> 4;
    const int bg = lane >> 3;
    const int kb0 = bg & 1;
    const uint32_t arow  = (uint32_t)(wm * 64 + (lane & 15)) * 128;
    const uint32_t brow0 = GOFF_B +
        (uint32_t)(wn * 32 + (lane & 7) + ((bg & 2) << 2)) * 128;

    float acc[4][4][4];
#pragma unroll
    for (int mt = 0; mt < 4; mt++)
#pragma unroll
        for (int nt = 0; nt < 4; nt++)
#pragma unroll
            for (int q = 0; q < 4; q++) acc[mt][nt][q] = 0.f;

    uint32_t Af[4][4];
    uint32_t Bf[2][4];

#define G_PROD(st_, c_)                                                          \
    {                                                                            \
        const uint32_t db = sb + (st_) * GST;                                    \
        const char* as = asrc + (size_t)(c_) * 128;                              \
        const char* bs = bsrc + (size_t)(c_) * 128;                              \
        _Pragma("unroll")                                                        \
        for (int t = 0; t < 4; t++) {                                            \
            uint32_t so = SW128(pb + t * 16);                                    \
            cpa16(db + so, as + t * 16);                                         \
            cpa16(db + GOFF_B + so, bs + t * 16);                                \
        }                                                                        \
        CPA_COMMIT();                                                            \
    }

    G_PROD(0, 0);
    G_PROD(1, 1);

    for (int c = 0; c < NCHUNK_KQ; c++) {
        const int st = c % 3;
        if (c + 1 >= NCHUNK_KQ) { CPA_WAIT0(); } else { CPA_WAIT1(); }
        __syncthreads();
        if (c + 2 < NCHUNK_KQ) G_PROD((c + 2) % 3, c + 2);

        const uint32_t sbase = sb + st * GST;
#pragma unroll
        for (int ks = 0; ks < 4; ks++) {
            const int kcA = ks * 2 + alsel;
            const uint32_t ao = (uint32_t)((kcA ^ ksw) << 4);
            ldsm4(Af[0], sbase + arow + ao);
            ldsm4(Af[1], sbase + arow + 2048 + ao);
            ldsm4(Af[2], sbase + arow + 4096 + ao);
            ldsm4(Af[3], sbase + arow + 6144 + ao);
            const int kcB = ks * 2 + kb0;
            const uint32_t bo = (uint32_t)((kcB ^ ksw) << 4);
            ldsm4(Bf[0], sbase + brow0 + bo);
            ldsm4(Bf[1], sbase + brow0 + 2048 + bo);
#pragma unroll
            for (int mt = 0; mt < 4; mt++) {
                mma_f16(acc[mt][0], Af[mt], Bf[0][0], Bf[0][1]);
                mma_f16(acc[mt][1], Af[mt], Bf[0][2], Bf[0][3]);
                mma_f16(acc[mt][2], Af[mt], Bf[1][0], Bf[1][1]);
                mma_f16(acc[mt][3], Af[mt], Bf[1][2], Bf[1][3]);
            }
        }
    }

    float* base = g_pnum[kq];
#pragma unroll
    for (int mt = 0; mt < 4; mt++) {
        const int lr = wm * 64 + mt * 16 + (lane >> 2);
        float* o0 = base + (size_t)(row0 + lr) * FOUT + nbase;
        float* o1 = base + (size_t)(row0 + lr + 8) * FOUT + nbase;
#pragma unroll
        for (int nt = 0; nt < 4; nt++) {
            const int col = wn * 32 + nt * 8 + (lane & 3) * 2;
            float2 v0 = {acc[mt][nt][0], acc[mt][nt][1]};
            float2 v1 = {acc[mt][nt][2], acc[mt][nt][3]};
            *(float2*)&o0[col] = v0;
            *(float2*)&o1[col] = v1;
        }
    }
#undef G_PROD
}

// ---------------------------------------------------------------------------
// k_combine: sum K-split partials + normalize + mish
// ---------------------------------------------------------------------------
__global__ __launch_bounds__(256) void k_combine(float* __restrict__ out)
{
    const int idx = blockIdx.x * 256 + threadIdx.x;       // float4 index
    const int row = idx >> 6;
    const float4* p0 = (const float4*)g_pnum[0];
    const float4* p1 = (const float4*)g_pnum[1];
    const float4* p2 = (const float4*)g_pnum[2];
    const float4* p3 = (const float4*)g_pnum[3];
    float inv = __fdividef(1.f, g_den[row]);
    float4 a = p0[idx], b = p1[idx], c = p2[idx], d = p3[idx];
    float4 o;
    o.x = fast_mish(((a.x + b.x) + (c.x + d.x)) * inv);
    o.y = fast_mish(((a.y + b.y) + (c.y + d.y)) * inv);
    o.z = fast_mish(((a.z + b.z) + (c.z + d.z)) * inv);
    o.w = fast_mish(((a.w + b.w) + (c.w + d.w)) * inv);
    ((float4*)out)[idx] = o;
}

// ---------------------------------------------------------------------------
extern "C" void kernel_launch(void* const* d_in, const int* in_sizes, int n_in,
                              void* d_out, int out_size)
{
    const float* x   = (const float*)d_in[0];   // [8192, 512]
    const int*   adj = (const int*)  d_in[1];   // [8192, 8192]
    const float* w   = (const float*)d_in[2];   // [512, 256]
    const float* a   = (const float*)d_in[3];   // [512, 1]
    float* out = (float*)d_out;                 // [8192, 256]

    cudaFuncSetAttribute(k_xw_tc, cudaFuncAttributeMaxDynamicSharedMemorySize,
                         XT_SMEM);
    cudaFuncSetAttribute(k_gemm, cudaFuncAttributeMaxDynamicSharedMemorySize,
                         GEMM_SMEM);

    // Forked-stream capture: xw_tc (g_hT) runs concurrently with the
    // scores->wgen chain; both join before k_gemm.
    cudaStream_t s2;
    cudaStreamCreate(&s2);
    cudaEvent_t e1, e2;
    cudaEventCreateWithFlags(&e1, cudaEventDisableTiming);
    cudaEventCreateWithFlags(&e2, cudaEventDisableTiming);

    cudaEventRecord(e1, 0);
    cudaStreamWaitEvent(s2, e1, 0);
    k_xw_tc<<<dim3(64, 2), 256, XT_SMEM, s2>>>(x, w);
    cudaEventRecord(e2, s2);

    k_wa<<<64, 256>>>(w, a);
    k_scores_x<<<N_NODES / 8, 256>>>(x);
    k_wgen<<<N_NODES / 8, 256>>>(adj);

    cudaStreamWaitEvent(0, e2, 0);
    k_gemm<<<dim3(64, 2, NSPLIT), 256, GEMM_SMEM>>>();
    k_combine<<<(N_NODES * FOUT / 4) / 256, 256>>>(out);
}